// round 1
// baseline (speedup 1.0000x reference)
#include <cuda_runtime.h>
#include <math.h>

// ---------------------------------------------------------------------------
// HierarchicalVAE: fused MLP chain + diffvg-style rasterizer.
// B=128, P=2 paths, SEG=4 cubic segments, T=8 samples/seg (32 pts/path),
// canvas 28x28, AA=2 (56x56 subsamples).
// Outputs (flat concat, float32):
//   rendered [128,1,28,28], mu [128,64], logvar [128,64],
//   control_points [128,2,4,4,2], widths [128,2], alphas [128,2]
// ---------------------------------------------------------------------------

#define BATCH 128
#define HALFC 14.0f
#define SCALEC 12.0f

#define OUT_R  0
#define OUT_MU (BATCH*784)
#define OUT_LV (OUT_MU + BATCH*64)
#define OUT_CP (OUT_LV + BATCH*64)
#define OUT_W  (OUT_CP + BATCH*64)
#define OUT_A  (OUT_W + BATCH*2)

// scratch: bezier sample points + norms + widths/alphas
__device__ float g_qx[BATCH * 64];   // [b][p*32+m]
__device__ float g_qy[BATCH * 64];
__device__ float g_qq[BATCH * 64];
__device__ float g_wa[BATCH * 4];    // w0,w1,a0,a1

__device__ __forceinline__ float seluf(float x) {
    const float sc = 1.0507009873554805f;
    const float al = 1.6732632423543772f;
    return x > 0.0f ? sc * x : sc * al * (expf(x) - 1.0f);
}
__device__ __forceinline__ float lrelu(float x) { return x >= 0.0f ? x : 0.2f * x; }
__device__ __forceinline__ float sigm(float x)  { return 1.0f / (1.0f + expf(-x)); }

// ---------------------------------------------------------------------------
// Kernel 1: full MLP chain, one block per batch element.
// ---------------------------------------------------------------------------
__global__ __launch_bounds__(256) void mlp_kernel(
    const float* __restrict__ x,    const float* __restrict__ eps,
    const float* __restrict__ ew1,  const float* __restrict__ eb1,
    const float* __restrict__ ew2,  const float* __restrict__ eb2,
    const float* __restrict__ muw,  const float* __restrict__ mub,
    const float* __restrict__ lvw,  const float* __restrict__ lvb,
    const float* __restrict__ dw1,  const float* __restrict__ db1,
    const float* __restrict__ dw2,  const float* __restrict__ db2,
    const float* __restrict__ cpw,  const float* __restrict__ cpb,
    const float* __restrict__ rw1,  const float* __restrict__ rb1,
    const float* __restrict__ rw2,  const float* __restrict__ rb2,
    const float* __restrict__ wdw,  const float* __restrict__ wdb,
    const float* __restrict__ alw,  const float* __restrict__ alb,
    float* __restrict__ out)
{
    const int b   = blockIdx.x;
    const int tid = threadIdx.x;

    __shared__ float sx[784];
    __shared__ float h1[256];
    __shared__ float h2[256];
    __shared__ float smu[64];
    __shared__ float slv[64];
    __shared__ float zz[64];
    __shared__ float d1[512];
    __shared__ float d2h[512];
    __shared__ float hin[92];
    __shared__ float r1[512];
    __shared__ float pts[52];

    for (int i = tid; i < 784; i += 256) sx[i] = x[b * 784 + i];
    __syncthreads();

    // enc layer 1: 784 -> 256, leaky_relu 0.2
    {
        float a = eb1[tid];
        for (int i = 0; i < 784; i++) a = fmaf(sx[i], ew1[i * 256 + tid], a);
        h1[tid] = lrelu(a);
    }
    __syncthreads();

    // enc layer 2: 256 -> 256
    {
        float a = eb2[tid];
        #pragma unroll 4
        for (int i = 0; i < 256; i++) a = fmaf(h1[i], ew2[i * 256 + tid], a);
        h2[tid] = lrelu(a);
    }
    __syncthreads();

    // mu / logvar: 256 -> 64 each
    if (tid < 64) {
        float a = mub[tid];
        #pragma unroll 4
        for (int i = 0; i < 256; i++) a = fmaf(h2[i], muw[i * 64 + tid], a);
        smu[tid] = a;
    } else if (tid < 128) {
        int j = tid - 64;
        float a = lvb[j];
        #pragma unroll 4
        for (int i = 0; i < 256; i++) a = fmaf(h2[i], lvw[i * 64 + j], a);
        slv[j] = a;
    }
    __syncthreads();

    if (tid < 64) {
        float mu = smu[tid], lv = slv[tid];
        float zv = mu + eps[b * 64 + tid] * expf(0.5f * lv);
        zz[tid]  = zv;
        hin[tid] = zv;
        out[OUT_MU + b * 64 + tid] = mu;
        out[OUT_LV + b * 64 + tid] = lv;
    }
    __syncthreads();

    // dec layer 1: 64 -> 512, selu
    for (int o = tid; o < 512; o += 256) {
        float a = db1[o];
        #pragma unroll
        for (int i = 0; i < 64; i++) a = fmaf(zz[i], dw1[i * 512 + o], a);
        d1[o] = seluf(a);
    }
    __syncthreads();

    // dec layer 2: 512 -> 512, selu
    for (int o = tid; o < 512; o += 256) {
        float a = db2[o];
        #pragma unroll 4
        for (int i = 0; i < 512; i++) a = fmaf(d1[i], dw2[i * 512 + o], a);
        d2h[o] = seluf(a);
    }
    __syncthreads();

    // coarse control points: 512 -> 28, tanh  (pts_norm == tanh values)
    if (tid < 28) {
        float a = cpb[tid];
        #pragma unroll 4
        for (int i = 0; i < 512; i++) a = fmaf(d2h[i], cpw[i * 28 + tid], a);
        hin[64 + tid] = tanhf(a);
    } else if (tid < 32) {
        // widths (k=0,1) and alphas (k=2,3): 512 -> 2 each
        int k = tid - 28;
        int p = k & 1;
        const float* w  = (k < 2) ? wdw : alw;
        const float* bb = (k < 2) ? wdb : alb;
        float a = bb[p];
        #pragma unroll 4
        for (int i = 0; i < 512; i++) a = fmaf(d2h[i], w[i * 2 + p], a);
        float s = sigm(a);
        if (k < 2) {
            float wv = s * 2.0f + 1.0f;
            out[OUT_W + b * 2 + p] = wv;
            g_wa[b * 4 + p] = wv;
        } else {
            out[OUT_A + b * 2 + p] = s;
            g_wa[b * 4 + 2 + p] = s;
        }
    }
    __syncthreads();

    // refine layer 1: 92 -> 512, selu
    for (int o = tid; o < 512; o += 256) {
        float a = rb1[o];
        #pragma unroll
        for (int i = 0; i < 92; i++) a = fmaf(hin[i], rw1[i * 512 + o], a);
        r1[o] = seluf(a);
    }
    __syncthreads();

    // refine layer 2: 512 -> 52, tanh, scale to canvas
    if (tid < 52) {
        float a = rb2[tid];
        #pragma unroll 4
        for (int i = 0; i < 512; i++) a = fmaf(r1[i], rw2[i * 52 + tid], a);
        pts[tid] = tanhf(a) * SCALEC + HALFC;
    }
    __syncthreads();

    if (tid < 64) {
        // control_points output: [p,s,k,d] -> points[p, 3s+k, d]
        int p = tid >> 5, rem = tid & 31;
        int s = rem >> 3, k = (rem >> 1) & 3, d = rem & 1;
        out[OUT_CP + b * 64 + tid] = pts[p * 26 + (3 * s + k) * 2 + d];

        // bezier sample point m for path p (tid<64: p in {0,1}, m in [0,32))
        int m = rem;                 // reuse: tid = p*32 + m
        int ss = m >> 3, ti = m & 7;
        float t  = (float)ti / 7.0f;
        float mt = 1.0f - t;
        float b0 = mt * mt * mt;
        float b1 = 3.0f * mt * mt * t;
        float b2 = 3.0f * mt * t * t;
        float b3 = t * t * t;
        int base = p * 26 + (3 * ss) * 2;
        float qx = b0 * pts[base + 0] + b1 * pts[base + 2] + b2 * pts[base + 4] + b3 * pts[base + 6];
        float qy = b0 * pts[base + 1] + b1 * pts[base + 3] + b2 * pts[base + 5] + b3 * pts[base + 7];
        g_qx[b * 64 + tid] = qx;
        g_qy[b * 64 + tid] = qy;
        g_qq[b * 64 + tid] = qx * qx + qy * qy;
    }
}

// ---------------------------------------------------------------------------
// Kernel 2: rasterizer. grid = (128, 4), block = 196 threads; 1 thread = 1 px.
// ---------------------------------------------------------------------------
__global__ void raster_kernel(float* __restrict__ out)
{
    const int b   = blockIdx.x;
    const int tid = threadIdx.x;

    __shared__ float qx[64], qy[64], qq[64], wa[4];
    if (tid < 64) {
        qx[tid] = g_qx[b * 64 + tid];
        qy[tid] = g_qy[b * 64 + tid];
        qq[tid] = g_qq[b * 64 + tid];
    }
    if (tid < 4) wa[tid] = g_wa[b * 4 + tid];
    __syncthreads();

    int px = blockIdx.y * 196 + tid;
    if (px >= 784) return;
    int pi = px / 28;   // row
    int pj = px % 28;   // col

    float acc = 0.0f;
    #pragma unroll
    for (int dy = 0; dy < 2; dy++) {
        #pragma unroll
        for (int dx = 0; dx < 2; dx++) {
            float sy = ((float)(2 * pi + dy) + 0.5f) * 0.5f;
            float sx = ((float)(2 * pj + dx) + 0.5f) * 0.5f;
            float ssn = sx * sx + sy * sy;

            float val = 1.0f;
            #pragma unroll
            for (int p = 0; p < 2; p++) {
                int base = p * 32;
                float mind2 = 3.402823e38f;
                int nc = 0;
                float x0 = qx[base], y0 = qy[base];
                bool c0 = y0 > sy;
                #pragma unroll 4
                for (int m = 0; m < 32; m++) {
                    // distance term for point m (== current x0,y0)
                    float v = fmaf(-2.0f * sx, x0, fmaf(-2.0f * sy, y0, qq[base + m] + ssn));
                    v = fmaxf(v, 0.0f);
                    mind2 = fminf(mind2, v);
                    // edge m -> (m+1)%32
                    int mn = (m + 1) & 31;
                    float x1 = qx[base + mn], y1 = qy[base + mn];
                    bool c1 = y1 > sy;
                    if (c0 != c1) {
                        float te   = __fdiv_rn(sy - y0, (y1 - y0) + 1e-8f);
                        float xint = fmaf(te, x1 - x0, x0);
                        if (sx < xint) nc++;
                    }
                    x0 = x1; y0 = y1; c0 = c1;
                }
                float dist   = sqrtf(mind2);
                float stroke = fminf(fmaxf(fmaf(wa[p], 0.5f, 0.5f) - dist, 0.0f), 1.0f);
                float cov    = fmaxf((float)(nc & 1), stroke);
                val *= 1.0f - wa[2 + p] * cov;
            }
            acc += val;
        }
    }
    // rendered = 1 - mean(img subsamples)
    out[OUT_R + b * 784 + px] = 1.0f - 0.25f * acc;
}

// ---------------------------------------------------------------------------
extern "C" void kernel_launch(void* const* d_in, const int* in_sizes, int n_in,
                              void* d_out, int out_size)
{
    const float* x    = (const float*)d_in[0];
    const float* eps  = (const float*)d_in[1];
    const float* ew1  = (const float*)d_in[2];
    const float* eb1  = (const float*)d_in[3];
    const float* ew2  = (const float*)d_in[4];
    const float* eb2  = (const float*)d_in[5];
    const float* muw  = (const float*)d_in[6];
    const float* mub  = (const float*)d_in[7];
    const float* lvw  = (const float*)d_in[8];
    const float* lvb  = (const float*)d_in[9];
    const float* dw1  = (const float*)d_in[10];
    const float* db1  = (const float*)d_in[11];
    const float* dw2  = (const float*)d_in[12];
    const float* db2  = (const float*)d_in[13];
    const float* cpw  = (const float*)d_in[14];
    const float* cpb  = (const float*)d_in[15];
    const float* rw1  = (const float*)d_in[16];
    const float* rb1  = (const float*)d_in[17];
    const float* rw2  = (const float*)d_in[18];
    const float* rb2  = (const float*)d_in[19];
    const float* wdw  = (const float*)d_in[20];
    const float* wdb  = (const float*)d_in[21];
    const float* alw  = (const float*)d_in[22];
    const float* alb  = (const float*)d_in[23];
    float* out = (float*)d_out;

    mlp_kernel<<<BATCH, 256>>>(x, eps, ew1, eb1, ew2, eb2, muw, mub, lvw, lvb,
                               dw1, db1, dw2, db2, cpw, cpb, rw1, rb1, rw2, rb2,
                               wdw, wdb, alw, alb, out);
    raster_kernel<<<dim3(BATCH, 4), 196>>>(out);
}

// round 2
// speedup vs baseline: 2.0657x; 2.0657x over previous
#include <cuda_runtime.h>
#include <math.h>
#include <stdint.h>

// ---------------------------------------------------------------------------
// HierarchicalVAE fused: cp.async-pipelined MLP chain + in-CTA rasterizer.
// grid = 128 (one CTA per batch element), block = 256.
// Weights streamed through a 3-stage x 64KB smem ring (lookahead 2 tiles),
// one continuous tile sequence across all layers.
// ---------------------------------------------------------------------------

#define BATCH 128
#define TPB 256
#define STAGE_FLOATS 16384          // 64KB per stage
#define NSTAGES 3
#define HALFC 14.0f
#define SCALEC 12.0f

#define OUT_R  0
#define OUT_MU (BATCH*784)
#define OUT_LV (OUT_MU + BATCH*64)
#define OUT_CP (OUT_LV + BATCH*64)
#define OUT_W  (OUT_CP + BATCH*64)
#define OUT_A  (OUT_W + BATCH*2)

struct WPtrs {
    const float *ew1, *ew2, *muw, *lvw, *dw1, *dw2, *cpw, *wdw, *alw, *rw1, *rw2;
};

__device__ __forceinline__ void cp_async16(void* dst, const void* src) {
    uint32_t d = (uint32_t)__cvta_generic_to_shared(dst);
    asm volatile("cp.async.cg.shared.global [%0], [%1], 16;" :: "r"(d), "l"(src));
}
__device__ __forceinline__ void cp_commit() { asm volatile("cp.async.commit_group;" ::: "memory"); }
__device__ __forceinline__ void cp_wait2()  { asm volatile("cp.async.wait_group 2;" ::: "memory"); }

__device__ __forceinline__ float seluf(float x) {
    const float sc = 1.0507009873554805f;
    const float al = 1.6732632423543772f;
    return x > 0.0f ? sc * x : sc * al * (expf(x) - 1.0f);
}
__device__ __forceinline__ float lrelu(float x) { return x >= 0.0f ? x : 0.2f * x; }
__device__ __forceinline__ float sigm(float x)  { return 1.0f / (1.0f + expf(-x)); }

// Global tile sequence (45 tiles):
//  [0,13)  enc1  784x256, 64-row tiles (last 16)
//  [13,17) enc2  256x256, 64-row tiles
//  [17]    muw   256x64   whole
//  [18]    lvw   256x64   whole
//  [19,21) dec1  64x512,  32-row tiles
//  [21,37) dec2  512x512, 32-row tiles
//  [37]    cpw   512x28   whole
//  [38]    wdw   512x2    whole
//  [39]    alw   512x2    whole
//  [40,43) ref1  92x512,  32-row tiles (last 28)
//  [43,45) rw2   512x52,  256-row tiles
__device__ __forceinline__ const char* tile_src(int n, int& bytes, const WPtrs& p) {
    if (n < 13) { int r0 = n * 64; int rows = (r0 + 64 <= 784) ? 64 : (784 - r0);
                  bytes = rows * 256 * 4; return (const char*)(p.ew1 + r0 * 256); }
    n -= 13;
    if (n < 4)  { bytes = 64 * 256 * 4; return (const char*)(p.ew2 + n * 64 * 256); }
    n -= 4;
    if (n == 0) { bytes = 256 * 64 * 4; return (const char*)p.muw; } n--;
    if (n == 0) { bytes = 256 * 64 * 4; return (const char*)p.lvw; } n--;
    if (n < 2)  { bytes = 32 * 512 * 4; return (const char*)(p.dw1 + n * 32 * 512); }
    n -= 2;
    if (n < 16) { bytes = 32 * 512 * 4; return (const char*)(p.dw2 + n * 32 * 512); }
    n -= 16;
    if (n == 0) { bytes = 512 * 28 * 4; return (const char*)p.cpw; } n--;
    if (n == 0) { bytes = 512 * 2 * 4;  return (const char*)p.wdw; } n--;
    if (n == 0) { bytes = 512 * 2 * 4;  return (const char*)p.alw; } n--;
    if (n < 3)  { int r0 = n * 32; int rows = (r0 + 32 <= 92) ? 32 : (92 - r0);
                  bytes = rows * 512 * 4; return (const char*)(p.rw1 + r0 * 512); }
    n -= 3;
    if (n < 2)  { bytes = 256 * 52 * 4; return (const char*)(p.rw2 + n * 256 * 52); }
    bytes = 0; return nullptr;
}

__device__ __forceinline__ void issue_tile(float* wb, int n, const WPtrs& p, int tid) {
    int bytes; const char* src = tile_src(n, bytes, p);
    if (src) {
        char* dst = (char*)(wb + (n % NSTAGES) * STAGE_FLOATS);
        for (int off = tid * 16; off < bytes; off += TPB * 16)
            cp_async16(dst + off, src + off);
    }
    cp_commit();   // every thread, every step (empty groups complete immediately)
}

#define TILE_BEGIN()  do { issue_tile(wb, tn + 2, wp, tid); cp_wait2(); __syncthreads(); \
                           ws = wb + (tn % NSTAGES) * STAGE_FLOATS; } while (0)
#define TILE_END()    do { __syncthreads(); tn++; } while (0)

__global__ __launch_bounds__(TPB, 1) void fused_kernel(
    const float* __restrict__ x,    const float* __restrict__ eps,
    const float* __restrict__ ew1,  const float* __restrict__ eb1,
    const float* __restrict__ ew2,  const float* __restrict__ eb2,
    const float* __restrict__ muw,  const float* __restrict__ mub,
    const float* __restrict__ lvw,  const float* __restrict__ lvb,
    const float* __restrict__ dw1,  const float* __restrict__ db1,
    const float* __restrict__ dw2,  const float* __restrict__ db2,
    const float* __restrict__ cpw,  const float* __restrict__ cpb,
    const float* __restrict__ rw1,  const float* __restrict__ rb1,
    const float* __restrict__ rw2w, const float* __restrict__ rb2,
    const float* __restrict__ wdw,  const float* __restrict__ wdb,
    const float* __restrict__ alw,  const float* __restrict__ alb,
    float* __restrict__ out)
{
    extern __shared__ float wb[];   // NSTAGES * STAGE_FLOATS

    const int b   = blockIdx.x;
    const int tid = threadIdx.x;

    __shared__ float sx[784];
    __shared__ float h1[256];
    __shared__ float h2[256];
    __shared__ float muv[64];
    __shared__ float hin[92];       // z (0..63) + tanh coarse (64..91)
    __shared__ float d1[512];
    __shared__ float d2[512];
    __shared__ float r1[512];
    __shared__ float pts[52];
    __shared__ float red[256];
    __shared__ float qx[64], qy[64], qq[64], sinv[64], wa[4];

    WPtrs wp; wp.ew1 = ew1; wp.ew2 = ew2; wp.muw = muw; wp.lvw = lvw;
    wp.dw1 = dw1; wp.dw2 = dw2; wp.cpw = cpw; wp.wdw = wdw; wp.alw = alw;
    wp.rw1 = rw1; wp.rw2 = rw2w;

    int tn = 0;
    float* ws;

    // prologue: 2 tiles in flight; stage x meanwhile
    issue_tile(wb, 0, wp, tid);
    issue_tile(wb, 1, wp, tid);
    for (int i = tid; i < 784; i += TPB) sx[i] = x[b * 784 + i];

    // ---------------- enc1: 784 -> 256, leaky_relu ----------------
    {
        float acc = eb1[tid];
        for (int t = 0; t < 13; t++) {
            TILE_BEGIN();
            const int r0 = t * 64, rows = (t < 12) ? 64 : 16;
            #pragma unroll 4
            for (int r = 0; r < rows; r++)
                acc = fmaf(sx[r0 + r], ws[r * 256 + tid], acc);
            TILE_END();
        }
        h1[tid] = lrelu(acc);
    }

    // ---------------- enc2: 256 -> 256, leaky_relu ----------------
    {
        float acc = eb2[tid];
        for (int t = 0; t < 4; t++) {
            TILE_BEGIN();
            const int r0 = t * 64;
            #pragma unroll 4
            for (int r = 0; r < 64; r++)
                acc = fmaf(h1[r0 + r], ws[r * 256 + tid], acc);
            TILE_END();
        }
        h2[tid] = lrelu(acc);
    }

    // ---------------- mu: 256 -> 64 (4-way K split) ----------------
    TILE_BEGIN();
    {
        const int g = tid >> 6, l = tid & 63;
        float a = 0.0f;
        #pragma unroll 4
        for (int i = 0; i < 64; i++) { int ii = g * 64 + i; a = fmaf(h2[ii], ws[ii * 64 + l], a); }
        red[tid] = a;
    }
    TILE_END();
    if (tid < 64)
        muv[tid] = mub[tid] + ((red[tid] + red[64 + tid]) + (red[128 + tid] + red[192 + tid]));

    // ---------------- logvar: 256 -> 64 ----------------
    TILE_BEGIN();
    {
        const int g = tid >> 6, l = tid & 63;
        float a = 0.0f;
        #pragma unroll 4
        for (int i = 0; i < 64; i++) { int ii = g * 64 + i; a = fmaf(h2[ii], ws[ii * 64 + l], a); }
        red[tid] = a;
    }
    TILE_END();
    if (tid < 64) {
        float lvV = lvb[tid] + ((red[tid] + red[64 + tid]) + (red[128 + tid] + red[192 + tid]));
        float m = muv[tid];
        out[OUT_MU + b * 64 + tid] = m;
        out[OUT_LV + b * 64 + tid] = lvV;
        hin[tid] = m + eps[b * 64 + tid] * expf(0.5f * lvV);   // z
    }

    // ---------------- dec1: 64 -> 512, selu ----------------
    {
        float a0 = db1[tid], a1 = db1[tid + 256];
        for (int t = 0; t < 2; t++) {
            TILE_BEGIN();
            const int r0 = t * 32;
            #pragma unroll 4
            for (int r = 0; r < 32; r++) {
                float av = hin[r0 + r];
                a0 = fmaf(av, ws[r * 512 + tid], a0);
                a1 = fmaf(av, ws[r * 512 + tid + 256], a1);
            }
            TILE_END();
        }
        d1[tid] = seluf(a0); d1[tid + 256] = seluf(a1);
    }

    // ---------------- dec2: 512 -> 512, selu ----------------
    {
        float a0 = db2[tid], a1 = db2[tid + 256];
        for (int t = 0; t < 16; t++) {
            TILE_BEGIN();
            const int r0 = t * 32;
            #pragma unroll 4
            for (int r = 0; r < 32; r++) {
                float av = d1[r0 + r];
                a0 = fmaf(av, ws[r * 512 + tid], a0);
                a1 = fmaf(av, ws[r * 512 + tid + 256], a1);
            }
            TILE_END();
        }
        d2[tid] = seluf(a0); d2[tid + 256] = seluf(a1);
    }

    // ---------------- coarse cp: 512 -> 28, tanh (8-way K split) ----------------
    TILE_BEGIN();
    {
        const int g = tid >> 5, l = tid & 31;
        float a = 0.0f;
        if (l < 28) {
            #pragma unroll 4
            for (int i = 0; i < 64; i++) { int ii = g * 64 + i; a = fmaf(d2[ii], ws[ii * 28 + l], a); }
        }
        red[tid] = a;
    }
    TILE_END();
    if (tid < 28) {
        float s = cpb[tid];
        #pragma unroll
        for (int k = 0; k < 8; k++) s += red[k * 32 + tid];
        hin[64 + tid] = tanhf(s);
    }

    // ---------------- widths: 512 -> 2 ----------------
    TILE_BEGIN();
    {
        const int pp = tid >> 7, l = tid & 127;
        float a = 0.0f;
        #pragma unroll
        for (int k = 0; k < 4; k++) { int i = l + k * 128; a = fmaf(d2[i], ws[i * 2 + pp], a); }
        red[tid] = a;
    }
    TILE_END();
    if (tid < 2) {
        const float* rp = &red[tid * 128];
        float s0 = 0, s1 = 0, s2 = 0, s3 = 0;
        #pragma unroll
        for (int j = 0; j < 32; j++) { s0 += rp[j]; s1 += rp[32 + j]; s2 += rp[64 + j]; s3 += rp[96 + j]; }
        float wv = sigm(wdb[tid] + ((s0 + s1) + (s2 + s3))) * 2.0f + 1.0f;
        wa[tid] = wv;
        out[OUT_W + b * 2 + tid] = wv;
    }

    // ---------------- alphas: 512 -> 2 ----------------
    TILE_BEGIN();
    {
        const int pp = tid >> 7, l = tid & 127;
        float a = 0.0f;
        #pragma unroll
        for (int k = 0; k < 4; k++) { int i = l + k * 128; a = fmaf(d2[i], ws[i * 2 + pp], a); }
        red[tid] = a;
    }
    TILE_END();
    if (tid < 2) {
        const float* rp = &red[tid * 128];
        float s0 = 0, s1 = 0, s2 = 0, s3 = 0;
        #pragma unroll
        for (int j = 0; j < 32; j++) { s0 += rp[j]; s1 += rp[32 + j]; s2 += rp[64 + j]; s3 += rp[96 + j]; }
        float av = sigm(alb[tid] + ((s0 + s1) + (s2 + s3)));
        wa[2 + tid] = av;
        out[OUT_A + b * 2 + tid] = av;
    }

    // ---------------- refine1: 92 -> 512, selu ----------------
    {
        float a0 = rb1[tid], a1 = rb1[tid + 256];
        for (int t = 0; t < 3; t++) {
            TILE_BEGIN();
            const int r0 = t * 32, rows = (t < 2) ? 32 : 28;
            #pragma unroll 4
            for (int r = 0; r < rows; r++) {
                float av = hin[r0 + r];
                a0 = fmaf(av, ws[r * 512 + tid], a0);
                a1 = fmaf(av, ws[r * 512 + tid + 256], a1);
            }
            TILE_END();
        }
        r1[tid] = seluf(a0); r1[tid + 256] = seluf(a1);
    }

    // ---------------- refine2: 512 -> 52, tanh*SCALE+HALF (4-way K split) ----------------
    {
        const int g = tid >> 6, l = tid & 63;
        float a = 0.0f;
        for (int t = 0; t < 2; t++) {
            TILE_BEGIN();
            if (l < 52) {
                #pragma unroll 4
                for (int i = 0; i < 64; i++) {
                    int ii = g * 64 + i;
                    a = fmaf(r1[t * 256 + ii], ws[ii * 52 + l], a);
                }
            }
            TILE_END();
        }
        red[tid] = a;
    }
    __syncthreads();
    if (tid < 52) {
        float s = rb2[tid] + ((red[tid] + red[64 + tid]) + (red[128 + tid] + red[192 + tid]));
        pts[tid] = tanhf(s) * SCALEC + HALFC;
    }
    __syncthreads();

    // ---------------- control points out + bezier sample eval ----------------
    if (tid < 64) {
        const int p = tid >> 5, rem = tid & 31;
        {
            int s = rem >> 3, k = (rem >> 1) & 3, d = rem & 1;
            out[OUT_CP + b * 64 + tid] = pts[p * 26 + (3 * s + k) * 2 + d];
        }
        const int ss = rem >> 3, ti = rem & 7;
        float t  = (float)ti / 7.0f;
        float mt = 1.0f - t;
        float b0 = mt * mt * mt;
        float b1 = 3.0f * mt * mt * t;
        float b2 = 3.0f * mt * t * t;
        float b3 = t * t * t;
        int base = p * 26 + (3 * ss) * 2;
        float X = b0 * pts[base + 0] + b1 * pts[base + 2] + b2 * pts[base + 4] + b3 * pts[base + 6];
        float Y = b0 * pts[base + 1] + b1 * pts[base + 3] + b2 * pts[base + 5] + b3 * pts[base + 7];
        qx[tid] = X; qy[tid] = Y; qq[tid] = X * X + Y * Y;
    }
    __syncthreads();
    if (tid < 64) {
        const int p = tid >> 5, m = tid & 31;
        float y0 = qy[tid];
        float y1 = qy[p * 32 + ((m + 1) & 31)];
        sinv[tid] = __fdiv_rn(1.0f, (y1 - y0) + 1e-8f);
    }
    __syncthreads();

    // ---------------- rasterizer (fused, per-CTA) ----------------
    for (int px = tid; px < 784; px += TPB) {
        const int pi = px / 28, pj = px - pi * 28;
        float acc = 0.0f;
        #pragma unroll
        for (int sub = 0; sub < 4; sub++) {
            const float sy  = (float)pi + (0.25f + 0.5f * (float)(sub >> 1));
            const float sxv = (float)pj + (0.25f + 0.5f * (float)(sub & 1));
            const float ssn = sxv * sxv + sy * sy;
            const float nx  = -2.0f * sxv, ny = -2.0f * sy;

            float val = 1.0f;
            #pragma unroll
            for (int p = 0; p < 2; p++) {
                const int base = p * 32;
                float mind2 = 3.402823e38f;
                int nc = 0;
                float x0 = qx[base], y0 = qy[base];
                bool c0 = y0 > sy;
                #pragma unroll 8
                for (int m = 0; m < 32; m++) {
                    const int mn = base + ((m + 1) & 31);
                    const float x1 = qx[mn], y1 = qy[mn];
                    float v = fmaf(nx, x0, fmaf(ny, y0, qq[base + m] + ssn));
                    mind2 = fminf(mind2, fmaxf(v, 0.0f));
                    const bool c1 = y1 > sy;
                    const float xint = fmaf((sy - y0) * sinv[base + m], x1 - x0, x0);
                    nc += (int)((c0 != c1) && (sxv < xint));
                    x0 = x1; y0 = y1; c0 = c1;
                }
                const float dist   = sqrtf(mind2);
                const float stroke = fminf(fmaxf(fmaf(wa[p], 0.5f, 0.5f) - dist, 0.0f), 1.0f);
                const float cov    = fmaxf((float)(nc & 1), stroke);
                val *= 1.0f - wa[2 + p] * cov;
            }
            acc += val;
        }
        out[OUT_R + b * 784 + px] = 1.0f - 0.25f * acc;
    }
}

// ---------------------------------------------------------------------------
extern "C" void kernel_launch(void* const* d_in, const int* in_sizes, int n_in,
                              void* d_out, int out_size)
{
    const float* x    = (const float*)d_in[0];
    const float* eps  = (const float*)d_in[1];
    const float* ew1  = (const float*)d_in[2];
    const float* eb1  = (const float*)d_in[3];
    const float* ew2  = (const float*)d_in[4];
    const float* eb2  = (const float*)d_in[5];
    const float* muw  = (const float*)d_in[6];
    const float* mub  = (const float*)d_in[7];
    const float* lvw  = (const float*)d_in[8];
    const float* lvb  = (const float*)d_in[9];
    const float* dw1  = (const float*)d_in[10];
    const float* db1  = (const float*)d_in[11];
    const float* dw2  = (const float*)d_in[12];
    const float* db2  = (const float*)d_in[13];
    const float* cpw  = (const float*)d_in[14];
    const float* cpb  = (const float*)d_in[15];
    const float* rw1  = (const float*)d_in[16];
    const float* rb1  = (const float*)d_in[17];
    const float* rw2  = (const float*)d_in[18];
    const float* rb2  = (const float*)d_in[19];
    const float* wdw  = (const float*)d_in[20];
    const float* wdb  = (const float*)d_in[21];
    const float* alw  = (const float*)d_in[22];
    const float* alb  = (const float*)d_in[23];
    float* out = (float*)d_out;

    const int dyn = NSTAGES * STAGE_FLOATS * 4;   // 196608 bytes
    cudaFuncSetAttribute(fused_kernel, cudaFuncAttributeMaxDynamicSharedMemorySize, dyn);
    fused_kernel<<<BATCH, TPB, dyn>>>(x, eps, ew1, eb1, ew2, eb2, muw, mub, lvw, lvb,
                                      dw1, db1, dw2, db2, cpw, cpb, rw1, rb1, rw2, rb2,
                                      wdw, wdb, alw, alb, out);
}

// round 4
// speedup vs baseline: 2.5513x; 1.2351x over previous
#include <cuda_runtime.h>
#include <math.h>
#include <stdint.h>

// ---------------------------------------------------------------------------
// HierarchicalVAE fused, cluster-4 multicast weight streaming.
// grid = 128 CTAs (1 per batch element), 32 clusters x 4 CTAs.
// Weights flow through a 6-stage x 32KB smem ring; each cluster rank bulk-loads
// 1/4 of each tile and multicasts it to all 4 CTAs (cp.async.bulk.multicast).
// mbarrier full/empty ring, lookahead 5 tiles. Raster fused at the end.
// R4 fix: __syncthreads() after epilogues that read red[] (race with next
// tile's red[] writes once TILE_BEGIN no longer contains a CTA barrier).
// ---------------------------------------------------------------------------

#define BATCH 128
#define TPB 256
#define CLUSTER 4
#define NSTAGES 6
#define STAGE_FLOATS 8192            // 32KB
#define NT 87
#define LOOK 5
#define HALFC 14.0f
#define SCALEC 12.0f

#define OUT_R  0
#define OUT_MU (BATCH*784)
#define OUT_LV (OUT_MU + BATCH*64)
#define OUT_CP (OUT_LV + BATCH*64)
#define OUT_W  (OUT_CP + BATCH*64)
#define OUT_A  (OUT_W + BATCH*2)

struct WPtrs {
    const float *ew1, *ew2, *muw, *lvw, *dw1, *dw2, *cpw, *wdw, *alw, *rw1, *rw2;
};

__device__ __forceinline__ uint32_t smem_u32(const void* p) {
    return (uint32_t)__cvta_generic_to_shared(p);
}

__device__ __forceinline__ void mbar_init(uint32_t addr, uint32_t count) {
    asm volatile("mbarrier.init.shared.b64 [%0], %1;" :: "r"(addr), "r"(count) : "memory");
}
__device__ __forceinline__ void mbar_wait(uint32_t addr, uint32_t parity) {
    asm volatile(
        "{\n\t.reg .pred P;\n"
        "W_%=:\n\t"
        "mbarrier.try_wait.parity.acquire.cta.shared::cta.b64 P, [%0], %1, 0x989680;\n\t"
        "@P bra.uni D_%=;\n\t"
        "bra.uni W_%=;\n"
        "D_%=:\n\t}"
        :: "r"(addr), "r"(parity) : "memory");
}
__device__ __forceinline__ void mbar_expect_tx(uint32_t addr, uint32_t bytes) {
    asm volatile("mbarrier.arrive.expect_tx.shared.b64 _, [%0], %1;"
                 :: "r"(addr), "r"(bytes) : "memory");
}
__device__ __forceinline__ void mbar_arrive_rank(uint32_t addr, uint32_t rank) {
    asm volatile(
        "{\n\t.reg .b32 ra;\n\t"
        "mapa.shared::cluster.u32 ra, %0, %1;\n\t"
        "mbarrier.arrive.shared::cluster.b64 _, [ra];\n\t}"
        :: "r"(addr), "r"(rank) : "memory");
}
__device__ __forceinline__ void cluster_sync_all() {
    asm volatile("barrier.cluster.arrive.aligned;" ::: "memory");
    asm volatile("barrier.cluster.wait.aligned;" ::: "memory");
}
__device__ __forceinline__ void bulk_mc(uint32_t dst, const void* src, uint32_t bytes,
                                        uint32_t mbar, uint16_t mask) {
    asm volatile(
        "cp.async.bulk.shared::cluster.global.mbarrier::complete_tx::bytes.multicast::cluster "
        "[%0], [%1], %2, [%3], %4;"
        :: "r"(dst), "l"(src), "r"(bytes), "r"(mbar), "h"(mask) : "memory");
}

__device__ __forceinline__ float seluf(float x) {
    const float sc = 1.0507009873554805f;
    const float al = 1.6732632423543772f;
    return x > 0.0f ? sc * x : sc * al * (expf(x) - 1.0f);
}
__device__ __forceinline__ float lrelu(float x) { return x >= 0.0f ? x : 0.2f * x; }
__device__ __forceinline__ float sigm(float x)  { return 1.0f / (1.0f + expf(-x)); }

// Tile table (87 tiles):
//  [0,25)  enc1 784x256, 32-row tiles (last 16)
//  [25,33) enc2 256x256, 32-row
//  [33,35) muw 256x64, 128-row
//  [35,37) lvw
//  [37,41) dec1 64x512, 16-row
//  [41,73) dec2 512x512, 16-row
//  [73,75) cpw 512x28, 256-row
//  [75]    wdw 512x2
//  [76]    alw 512x2
//  [77,83) rw1 92x512, 16-row (last 12)
//  [83,87) rw2 512x52, 128-row
__device__ __forceinline__ const char* tile_src(int n, int& bytes, const WPtrs& p) {
    if (n < 25) { int r0 = n * 32; int rows = (r0 + 32 <= 784) ? 32 : (784 - r0);
                  bytes = rows * 1024; return (const char*)(p.ew1 + r0 * 256); }
    n -= 25;
    if (n < 8)  { bytes = 32768; return (const char*)(p.ew2 + n * 32 * 256); }
    n -= 8;
    if (n < 2)  { bytes = 32768; return (const char*)(p.muw + n * 128 * 64); }
    n -= 2;
    if (n < 2)  { bytes = 32768; return (const char*)(p.lvw + n * 128 * 64); }
    n -= 2;
    if (n < 4)  { bytes = 32768; return (const char*)(p.dw1 + n * 16 * 512); }
    n -= 4;
    if (n < 32) { bytes = 32768; return (const char*)(p.dw2 + n * 16 * 512); }
    n -= 32;
    if (n < 2)  { bytes = 28672; return (const char*)(p.cpw + n * 256 * 28); }
    n -= 2;
    if (n == 0) { bytes = 4096; return (const char*)p.wdw; } n--;
    if (n == 0) { bytes = 4096; return (const char*)p.alw; } n--;
    if (n < 6)  { int r0 = n * 16; int rows = (r0 + 16 <= 92) ? 16 : (92 - r0);
                  bytes = rows * 2048; return (const char*)(p.rw1 + r0 * 512); }
    n -= 6;
    bytes = 26624; return (const char*)(p.rw2 + n * 128 * 52);
}

// tid0 only: wait slot empty, expect full tile, multicast this rank's quarter.
__device__ __forceinline__ void produce(int j, uint32_t bar_base, uint32_t ring_base,
                                        const WPtrs& p, uint32_t rank) {
    const int s = j % NSTAGES;
    mbar_wait(bar_base + s * 16 + 8, 1u ^ ((uint32_t)(j / NSTAGES) & 1u));
    int bytes; const char* src = tile_src(j, bytes, p);
    const uint32_t full = bar_base + s * 16;
    mbar_expect_tx(full, (uint32_t)bytes);
    const uint32_t slice = (uint32_t)bytes >> 2;   // /CLUSTER
    bulk_mc(ring_base + s * 32768 + rank * slice, src + rank * slice, slice, full, 0xF);
}

#define TILE_BEGIN() do { \
        if (tid == 0 && tn + LOOK < NT) produce(tn + LOOK, bar_base, ring_base, wp, rank); \
        mbar_wait(bar_base + (tn % NSTAGES) * 16, (uint32_t)(tn / NSTAGES) & 1u); \
        ws = wb + (tn % NSTAGES) * STAGE_FLOATS; } while (0)

#define TILE_END() do { __syncthreads(); \
        if (tid == 0) { uint32_t e = bar_base + (tn % NSTAGES) * 16 + 8; \
            mbar_arrive_rank(e, 0); mbar_arrive_rank(e, 1); \
            mbar_arrive_rank(e, 2); mbar_arrive_rank(e, 3); } \
        tn++; } while (0)

__global__ void __launch_bounds__(TPB, 1) __cluster_dims__(CLUSTER, 1, 1)
fused_kernel(
    const float* __restrict__ x,    const float* __restrict__ eps,
    const float* __restrict__ ew1,  const float* __restrict__ eb1,
    const float* __restrict__ ew2,  const float* __restrict__ eb2,
    const float* __restrict__ muw,  const float* __restrict__ mub,
    const float* __restrict__ lvw,  const float* __restrict__ lvb,
    const float* __restrict__ dw1,  const float* __restrict__ db1,
    const float* __restrict__ dw2,  const float* __restrict__ db2,
    const float* __restrict__ cpw,  const float* __restrict__ cpb,
    const float* __restrict__ rw1,  const float* __restrict__ rb1,
    const float* __restrict__ rw2w, const float* __restrict__ rb2,
    const float* __restrict__ wdw,  const float* __restrict__ wdb,
    const float* __restrict__ alw,  const float* __restrict__ alb,
    float* __restrict__ out)
{
    extern __shared__ float wb[];   // NSTAGES * STAGE_FLOATS

    const int b   = blockIdx.x;
    const int tid = threadIdx.x;

    __shared__ alignas(16) unsigned long long mbars[NSTAGES * 2]; // [full,empty] x 6
    __shared__ float sx[784];
    __shared__ float h1[256];
    __shared__ float h2[256];
    __shared__ float muv[64];
    __shared__ float hin[92];       // z (0..63) + tanh coarse (64..91)
    __shared__ float d1[512];
    __shared__ float d2[512];
    __shared__ float r1[512];
    __shared__ float pts[52];
    __shared__ float red[256];
    __shared__ float qx[64], qy[64], qq[64], sinv[64], wa[4];

    WPtrs wp; wp.ew1 = ew1; wp.ew2 = ew2; wp.muw = muw; wp.lvw = lvw;
    wp.dw1 = dw1; wp.dw2 = dw2; wp.cpw = cpw; wp.wdw = wdw; wp.alw = alw;
    wp.rw1 = rw1; wp.rw2 = rw2w;

    const uint32_t bar_base  = smem_u32(mbars);
    const uint32_t ring_base = smem_u32(wb);
    uint32_t rank;
    asm("mov.u32 %0, %%cluster_ctarank;" : "=r"(rank));

    if (tid == 0) {
        #pragma unroll
        for (int s = 0; s < NSTAGES; s++) {
            mbar_init(bar_base + s * 16, 1);        // full: 1 local expect_tx arrive
            mbar_init(bar_base + s * 16 + 8, 4);    // empty: 1 arrive per cluster CTA
        }
    }
    __syncthreads();
    cluster_sync_all();   // barriers visible cluster-wide before any multicast

    if (tid == 0) {
        #pragma unroll
        for (int j = 0; j < LOOK; j++) produce(j, bar_base, ring_base, wp, rank);
    }
    for (int i = tid; i < 784; i += TPB) sx[i] = x[b * 784 + i];
    __syncthreads();

    int tn = 0;
    float* ws;

    // ---------------- enc1: 784 -> 256, leaky_relu (25 tiles) ----------------
    {
        float acc = eb1[tid];
        for (int t = 0; t < 25; t++) {
            TILE_BEGIN();
            const int r0 = t * 32, rows = (t < 24) ? 32 : 16;
            #pragma unroll 8
            for (int r = 0; r < rows; r++)
                acc = fmaf(sx[r0 + r], ws[r * 256 + tid], acc);
            TILE_END();
        }
        h1[tid] = lrelu(acc);
    }
    __syncthreads();

    // ---------------- enc2: 256 -> 256 (8 tiles) ----------------
    {
        float acc = eb2[tid];
        for (int t = 0; t < 8; t++) {
            TILE_BEGIN();
            const int r0 = t * 32;
            #pragma unroll 8
            for (int r = 0; r < 32; r++)
                acc = fmaf(h1[r0 + r], ws[r * 256 + tid], acc);
            TILE_END();
        }
        h2[tid] = lrelu(acc);
    }
    __syncthreads();

    // ---------------- mu: 256 -> 64 (2 tiles, 4-way K split) ----------------
    {
        const int g = tid >> 6, l = tid & 63;
        float a = 0.0f;
        for (int t = 0; t < 2; t++) {
            TILE_BEGIN();
            #pragma unroll 8
            for (int i = 0; i < 32; i++) {
                int kl = g * 32 + i;
                a = fmaf(h2[t * 128 + kl], ws[kl * 64 + l], a);
            }
            TILE_END();
        }
        red[tid] = a;
    }
    __syncthreads();
    if (tid < 64)
        muv[tid] = mub[tid] + ((red[tid] + red[64 + tid]) + (red[128 + tid] + red[192 + tid]));
    __syncthreads();

    // ---------------- logvar: 256 -> 64 (2 tiles) ----------------
    {
        const int g = tid >> 6, l = tid & 63;
        float a = 0.0f;
        for (int t = 0; t < 2; t++) {
            TILE_BEGIN();
            #pragma unroll 8
            for (int i = 0; i < 32; i++) {
                int kl = g * 32 + i;
                a = fmaf(h2[t * 128 + kl], ws[kl * 64 + l], a);
            }
            TILE_END();
        }
        red[tid] = a;
    }
    __syncthreads();
    if (tid < 64) {
        float lvV = lvb[tid] + ((red[tid] + red[64 + tid]) + (red[128 + tid] + red[192 + tid]));
        float m = muv[tid];
        out[OUT_MU + b * 64 + tid] = m;
        out[OUT_LV + b * 64 + tid] = lvV;
        hin[tid] = m + eps[b * 64 + tid] * expf(0.5f * lvV);   // z
    }
    __syncthreads();

    // ---------------- dec1: 64 -> 512, selu (4 tiles) ----------------
    {
        float a0 = db1[tid], a1 = db1[tid + 256];
        for (int t = 0; t < 4; t++) {
            TILE_BEGIN();
            const int r0 = t * 16;
            #pragma unroll
            for (int r = 0; r < 16; r++) {
                float av = hin[r0 + r];
                a0 = fmaf(av, ws[r * 512 + tid], a0);
                a1 = fmaf(av, ws[r * 512 + tid + 256], a1);
            }
            TILE_END();
        }
        d1[tid] = seluf(a0); d1[tid + 256] = seluf(a1);
    }
    __syncthreads();

    // ---------------- dec2: 512 -> 512, selu (32 tiles) ----------------
    {
        float a0 = db2[tid], a1 = db2[tid + 256];
        for (int t = 0; t < 32; t++) {
            TILE_BEGIN();
            const int r0 = t * 16;
            #pragma unroll
            for (int r = 0; r < 16; r++) {
                float av = d1[r0 + r];
                a0 = fmaf(av, ws[r * 512 + tid], a0);
                a1 = fmaf(av, ws[r * 512 + tid + 256], a1);
            }
            TILE_END();
        }
        d2[tid] = seluf(a0); d2[tid + 256] = seluf(a1);
    }
    __syncthreads();

    // ---------------- coarse cp: 512 -> 28, tanh (2 tiles, 8-way K split) ----------------
    {
        const int g = tid >> 5, l = tid & 31;
        float a = 0.0f;
        for (int t = 0; t < 2; t++) {
            TILE_BEGIN();
            if (l < 28) {
                #pragma unroll 8
                for (int i = 0; i < 32; i++) {
                    int kl = g * 32 + i;
                    a = fmaf(d2[t * 256 + kl], ws[kl * 28 + l], a);
                }
            }
            TILE_END();
        }
        red[tid] = a;
    }
    __syncthreads();
    if (tid < 28) {
        float s = cpb[tid];
        #pragma unroll
        for (int k = 0; k < 8; k++) s += red[k * 32 + tid];
        hin[64 + tid] = tanhf(s);
    }
    __syncthreads();

    // ---------------- widths: 512 -> 2 (1 tile) ----------------
    TILE_BEGIN();
    {
        const int pp = tid >> 7, l = tid & 127;
        float a = 0.0f;
        #pragma unroll
        for (int k = 0; k < 4; k++) { int i = l + k * 128; a = fmaf(d2[i], ws[i * 2 + pp], a); }
        red[tid] = a;
    }
    TILE_END();
    if (tid < 2) {
        const float* rp = &red[tid * 128];
        float s0 = 0, s1 = 0, s2 = 0, s3 = 0;
        #pragma unroll
        for (int j = 0; j < 32; j++) { s0 += rp[j]; s1 += rp[32 + j]; s2 += rp[64 + j]; s3 += rp[96 + j]; }
        float wv = sigm(wdb[tid] + ((s0 + s1) + (s2 + s3))) * 2.0f + 1.0f;
        wa[tid] = wv;
        out[OUT_W + b * 2 + tid] = wv;
    }
    __syncthreads();   // R4 FIX: protect red[] reads above from alphas' red[] writes

    // ---------------- alphas: 512 -> 2 (1 tile) ----------------
    TILE_BEGIN();
    {
        const int pp = tid >> 7, l = tid & 127;
        float a = 0.0f;
        #pragma unroll
        for (int k = 0; k < 4; k++) { int i = l + k * 128; a = fmaf(d2[i], ws[i * 2 + pp], a); }
        red[tid] = a;
    }
    TILE_END();
    if (tid < 2) {
        const float* rp = &red[tid * 128];
        float s0 = 0, s1 = 0, s2 = 0, s3 = 0;
        #pragma unroll
        for (int j = 0; j < 32; j++) { s0 += rp[j]; s1 += rp[32 + j]; s2 += rp[64 + j]; s3 += rp[96 + j]; }
        float av = sigm(alb[tid] + ((s0 + s1) + (s2 + s3)));
        wa[2 + tid] = av;
        out[OUT_A + b * 2 + tid] = av;
    }
    __syncthreads();   // R4 FIX: protect red[] reads above from later writes

    // ---------------- refine1: 92 -> 512, selu (6 tiles) ----------------
    {
        float a0 = rb1[tid], a1 = rb1[tid + 256];
        for (int t = 0; t < 6; t++) {
            TILE_BEGIN();
            const int r0 = t * 16, rows = (t < 5) ? 16 : 12;
            #pragma unroll
            for (int r = 0; r < rows; r++) {
                float av = hin[r0 + r];
                a0 = fmaf(av, ws[r * 512 + tid], a0);
                a1 = fmaf(av, ws[r * 512 + tid + 256], a1);
            }
            TILE_END();
        }
        r1[tid] = seluf(a0); r1[tid + 256] = seluf(a1);
    }
    __syncthreads();

    // ---------------- refine2: 512 -> 52 (4 tiles, 4-way K split) ----------------
    {
        const int g = tid >> 6, l = tid & 63;
        float a = 0.0f;
        for (int t = 0; t < 4; t++) {
            TILE_BEGIN();
            if (l < 52) {
                #pragma unroll 8
                for (int i = 0; i < 32; i++) {
                    int kl = g * 32 + i;
                    a = fmaf(r1[t * 128 + kl], ws[kl * 52 + l], a);
                }
            }
            TILE_END();
        }
        red[tid] = a;
    }
    __syncthreads();
    if (tid < 52) {
        float s = rb2[tid] + ((red[tid] + red[64 + tid]) + (red[128 + tid] + red[192 + tid]));
        pts[tid] = tanhf(s) * SCALEC + HALFC;
    }
    __syncthreads();

    // ---------------- control points out + bezier sample eval ----------------
    if (tid < 64) {
        const int p = tid >> 5, rem = tid & 31;
        {
            int s = rem >> 3, k = (rem >> 1) & 3, d = rem & 1;
            out[OUT_CP + b * 64 + tid] = pts[p * 26 + (3 * s + k) * 2 + d];
        }
        const int ss = rem >> 3, ti = rem & 7;
        float t  = (float)ti / 7.0f;
        float mt = 1.0f - t;
        float b0 = mt * mt * mt;
        float b1 = 3.0f * mt * mt * t;
        float b2 = 3.0f * mt * t * t;
        float b3 = t * t * t;
        int base = p * 26 + (3 * ss) * 2;
        float X = b0 * pts[base + 0] + b1 * pts[base + 2] + b2 * pts[base + 4] + b3 * pts[base + 6];
        float Y = b0 * pts[base + 1] + b1 * pts[base + 3] + b2 * pts[base + 5] + b3 * pts[base + 7];
        qx[tid] = X; qy[tid] = Y; qq[tid] = X * X + Y * Y;
    }
    __syncthreads();
    if (tid < 64) {
        const int p = tid >> 5, m = tid & 31;
        float y0 = qy[tid];
        float y1 = qy[p * 32 + ((m + 1) & 31)];
        sinv[tid] = __fdiv_rn(1.0f, (y1 - y0) + 1e-8f);
    }
    __syncthreads();

    // ---------------- rasterizer ----------------
    for (int px = tid; px < 784; px += TPB) {
        const int pi = px / 28, pj = px - pi * 28;
        float acc = 0.0f;
        #pragma unroll
        for (int sub = 0; sub < 4; sub++) {
            const float sy  = (float)pi + (0.25f + 0.5f * (float)(sub >> 1));
            const float sxv = (float)pj + (0.25f + 0.5f * (float)(sub & 1));
            const float ssn = sxv * sxv + sy * sy;
            const float nx  = -2.0f * sxv, ny = -2.0f * sy;

            float val = 1.0f;
            #pragma unroll
            for (int p = 0; p < 2; p++) {
                const int base = p * 32;
                float mind2 = 3.402823e38f;
                int nc = 0;
                float x0 = qx[base], y0 = qy[base];
                bool c0 = y0 > sy;
                #pragma unroll 8
                for (int m = 0; m < 32; m++) {
                    const int mn = base + ((m + 1) & 31);
                    const float x1 = qx[mn], y1 = qy[mn];
                    float v = fmaf(nx, x0, fmaf(ny, y0, qq[base + m] + ssn));
                    mind2 = fminf(mind2, fmaxf(v, 0.0f));
                    const bool c1 = y1 > sy;
                    const float xint = fmaf((sy - y0) * sinv[base + m], x1 - x0, x0);
                    nc += (int)((c0 != c1) && (sxv < xint));
                    x0 = x1; y0 = y1; c0 = c1;
                }
                const float dist   = sqrtf(mind2);
                const float stroke = fminf(fmaxf(fmaf(wa[p], 0.5f, 0.5f) - dist, 0.0f), 1.0f);
                const float cov    = fmaxf((float)(nc & 1), stroke);
                val *= 1.0f - wa[2 + p] * cov;
            }
            acc += val;
        }
        out[OUT_R + b * 784 + px] = 1.0f - 0.25f * acc;
    }

    cluster_sync_all();   // no CTA exits while peers might still multicast into it
}

// ---------------------------------------------------------------------------
extern "C" void kernel_launch(void* const* d_in, const int* in_sizes, int n_in,
                              void* d_out, int out_size)
{
    const float* x    = (const float*)d_in[0];
    const float* eps  = (const float*)d_in[1];
    const float* ew1  = (const float*)d_in[2];
    const float* eb1  = (const float*)d_in[3];
    const float* ew2  = (const float*)d_in[4];
    const float* eb2  = (const float*)d_in[5];
    const float* muw  = (const float*)d_in[6];
    const float* mub  = (const float*)d_in[7];
    const float* lvw  = (const float*)d_in[8];
    const float* lvb  = (const float*)d_in[9];
    const float* dw1  = (const float*)d_in[10];
    const float* db1  = (const float*)d_in[11];
    const float* dw2  = (const float*)d_in[12];
    const float* db2  = (const float*)d_in[13];
    const float* cpw  = (const float*)d_in[14];
    const float* cpb  = (const float*)d_in[15];
    const float* rw1  = (const float*)d_in[16];
    const float* rb1  = (const float*)d_in[17];
    const float* rw2  = (const float*)d_in[18];
    const float* rb2  = (const float*)d_in[19];
    const float* wdw  = (const float*)d_in[20];
    const float* wdb  = (const float*)d_in[21];
    const float* alw  = (const float*)d_in[22];
    const float* alb  = (const float*)d_in[23];
    float* out = (float*)d_out;

    const int dyn = NSTAGES * STAGE_FLOATS * 4;   // 196608 bytes
    cudaFuncSetAttribute(fused_kernel, cudaFuncAttributeMaxDynamicSharedMemorySize, dyn);
    fused_kernel<<<BATCH, TPB, dyn>>>(x, eps, ew1, eb1, ew2, eb2, muw, mub, lvw, lvb,
                                      dw1, db1, dw2, db2, cpw, cpb, rw1, rb1, rw2, rb2,
                                      wdw, wdb, alw, alb, out);
}

// round 5
// speedup vs baseline: 3.0786x; 1.2067x over previous
#include <cuda_runtime.h>
#include <math.h>
#include <stdint.h>

// ---------------------------------------------------------------------------
// HierarchicalVAE fused, cluster-4 multicast weight streaming,
// warp-specialized producer.
// grid = 128 CTAs (1 per batch element), 32 clusters x 4 CTAs, 288 threads:
//   warps 0-7 (256 thr): consumers — MLP chain + rasterizer
//   warp 8, thread 256:  producer — streams all 87 weight tiles through a
//                        6-stage x 32KB smem ring via cp.async.bulk.multicast
// Consumer syncs use named barrier 1 (256 threads) so the producer warp is
// never required at a barrier while it is still producing.
// ---------------------------------------------------------------------------

#define BATCH 128
#define TPB 288
#define NCONS 256
#define CLUSTER 4
#define NSTAGES 6
#define STAGE_FLOATS 8192            // 32KB
#define NT 87
#define HALFC 14.0f
#define SCALEC 12.0f

#define OUT_R  0
#define OUT_MU (BATCH*784)
#define OUT_LV (OUT_MU + BATCH*64)
#define OUT_CP (OUT_LV + BATCH*64)
#define OUT_W  (OUT_CP + BATCH*64)
#define OUT_A  (OUT_W + BATCH*2)

struct WPtrs {
    const float *ew1, *ew2, *muw, *lvw, *dw1, *dw2, *cpw, *wdw, *alw, *rw1, *rw2;
};

__device__ __forceinline__ uint32_t smem_u32(const void* p) {
    return (uint32_t)__cvta_generic_to_shared(p);
}

__device__ __forceinline__ void mbar_init(uint32_t addr, uint32_t count) {
    asm volatile("mbarrier.init.shared.b64 [%0], %1;" :: "r"(addr), "r"(count) : "memory");
}
__device__ __forceinline__ void mbar_wait(uint32_t addr, uint32_t parity) {
    asm volatile(
        "{\n\t.reg .pred P;\n"
        "W_%=:\n\t"
        "mbarrier.try_wait.parity.acquire.cta.shared::cta.b64 P, [%0], %1, 0x989680;\n\t"
        "@P bra.uni D_%=;\n\t"
        "bra.uni W_%=;\n"
        "D_%=:\n\t}"
        :: "r"(addr), "r"(parity) : "memory");
}
__device__ __forceinline__ void mbar_expect_tx(uint32_t addr, uint32_t bytes) {
    asm volatile("mbarrier.arrive.expect_tx.shared.b64 _, [%0], %1;"
                 :: "r"(addr), "r"(bytes) : "memory");
}
__device__ __forceinline__ void mbar_arrive_rank(uint32_t addr, uint32_t rank) {
    asm volatile(
        "{\n\t.reg .b32 ra;\n\t"
        "mapa.shared::cluster.u32 ra, %0, %1;\n\t"
        "mbarrier.arrive.shared::cluster.b64 _, [ra];\n\t}"
        :: "r"(addr), "r"(rank) : "memory");
}
__device__ __forceinline__ void cluster_sync_all() {
    asm volatile("barrier.cluster.arrive.aligned;" ::: "memory");
    asm volatile("barrier.cluster.wait.aligned;" ::: "memory");
}
__device__ __forceinline__ void bulk_mc(uint32_t dst, const void* src, uint32_t bytes,
                                        uint32_t mbar, uint16_t mask) {
    asm volatile(
        "cp.async.bulk.shared::cluster.global.mbarrier::complete_tx::bytes.multicast::cluster "
        "[%0], [%1], %2, [%3], %4;"
        :: "r"(dst), "l"(src), "r"(bytes), "r"(mbar), "h"(mask) : "memory");
}

__device__ __forceinline__ float seluf(float x) {
    const float sc = 1.0507009873554805f;
    const float al = 1.6732632423543772f;
    return x > 0.0f ? sc * x : sc * al * (expf(x) - 1.0f);
}
__device__ __forceinline__ float lrelu(float x) { return x >= 0.0f ? x : 0.2f * x; }
__device__ __forceinline__ float sigm(float x)  { return 1.0f / (1.0f + expf(-x)); }

// Tile table (87 tiles) — identical to R4 (numerics preserved):
__device__ __forceinline__ const char* tile_src(int n, int& bytes, const WPtrs& p) {
    if (n < 25) { int r0 = n * 32; int rows = (r0 + 32 <= 784) ? 32 : (784 - r0);
                  bytes = rows * 1024; return (const char*)(p.ew1 + r0 * 256); }
    n -= 25;
    if (n < 8)  { bytes = 32768; return (const char*)(p.ew2 + n * 32 * 256); }
    n -= 8;
    if (n < 2)  { bytes = 32768; return (const char*)(p.muw + n * 128 * 64); }
    n -= 2;
    if (n < 2)  { bytes = 32768; return (const char*)(p.lvw + n * 128 * 64); }
    n -= 2;
    if (n < 4)  { bytes = 32768; return (const char*)(p.dw1 + n * 16 * 512); }
    n -= 4;
    if (n < 32) { bytes = 32768; return (const char*)(p.dw2 + n * 16 * 512); }
    n -= 32;
    if (n < 2)  { bytes = 28672; return (const char*)(p.cpw + n * 256 * 28); }
    n -= 2;
    if (n == 0) { bytes = 4096; return (const char*)p.wdw; } n--;
    if (n == 0) { bytes = 4096; return (const char*)p.alw; } n--;
    if (n < 6)  { int r0 = n * 16; int rows = (r0 + 16 <= 92) ? 16 : (92 - r0);
                  bytes = rows * 2048; return (const char*)(p.rw1 + r0 * 512); }
    n -= 6;
    bytes = 26624; return (const char*)(p.rw2 + n * 128 * 52);
}

// producer thread: wait slot empty, expect full tile, multicast this rank's quarter.
__device__ __forceinline__ void produce(int j, uint32_t bar_base, uint32_t ring_base,
                                        const WPtrs& p, uint32_t rank) {
    const int s = j % NSTAGES;
    mbar_wait(bar_base + s * 16 + 8, 1u ^ ((uint32_t)(j / NSTAGES) & 1u));
    int bytes; const char* src = tile_src(j, bytes, p);
    const uint32_t full = bar_base + s * 16;
    mbar_expect_tx(full, (uint32_t)bytes);
    const uint32_t slice = (uint32_t)bytes >> 2;   // /CLUSTER
    bulk_mc(ring_base + s * 32768 + rank * slice, src + rank * slice, slice, full, 0xF);
}

#define CONS_SYNC() asm volatile("bar.sync 1, %0;" :: "n"(NCONS) : "memory")

#define TILE_BEGIN() do { \
        mbar_wait(bar_base + (tn % NSTAGES) * 16, (uint32_t)(tn / NSTAGES) & 1u); \
        ws = wb + (tn % NSTAGES) * STAGE_FLOATS; } while (0)

#define TILE_END() do { CONS_SYNC(); \
        if (tid == 0) { uint32_t e = bar_base + (tn % NSTAGES) * 16 + 8; \
            mbar_arrive_rank(e, 0); mbar_arrive_rank(e, 1); \
            mbar_arrive_rank(e, 2); mbar_arrive_rank(e, 3); } \
        tn++; } while (0)

__global__ void __launch_bounds__(TPB, 1) __cluster_dims__(CLUSTER, 1, 1)
fused_kernel(
    const float* __restrict__ x,    const float* __restrict__ eps,
    const float* __restrict__ ew1,  const float* __restrict__ eb1,
    const float* __restrict__ ew2,  const float* __restrict__ eb2,
    const float* __restrict__ muw,  const float* __restrict__ mub,
    const float* __restrict__ lvw,  const float* __restrict__ lvb,
    const float* __restrict__ dw1,  const float* __restrict__ db1,
    const float* __restrict__ dw2,  const float* __restrict__ db2,
    const float* __restrict__ cpw,  const float* __restrict__ cpb,
    const float* __restrict__ rw1,  const float* __restrict__ rb1,
    const float* __restrict__ rw2w, const float* __restrict__ rb2,
    const float* __restrict__ wdw,  const float* __restrict__ wdb,
    const float* __restrict__ alw,  const float* __restrict__ alb,
    float* __restrict__ out)
{
    extern __shared__ float wb[];   // NSTAGES * STAGE_FLOATS

    const int b   = blockIdx.x;
    const int tid = threadIdx.x;

    __shared__ alignas(16) unsigned long long mbars[NSTAGES * 2]; // [full,empty] x 6
    __shared__ float sx[784];
    __shared__ float h1[256];
    __shared__ float h2[256];
    __shared__ float muv[64];
    __shared__ float hin[92];       // z (0..63) + tanh coarse (64..91)
    __shared__ float d1[512];
    __shared__ float d2[512];
    __shared__ float r1[512];
    __shared__ float pts[52];
    __shared__ float red[256];
    __shared__ float qx[64], qy[64], qq[64], sinv[64], wa[4];

    WPtrs wp; wp.ew1 = ew1; wp.ew2 = ew2; wp.muw = muw; wp.lvw = lvw;
    wp.dw1 = dw1; wp.dw2 = dw2; wp.cpw = cpw; wp.wdw = wdw; wp.alw = alw;
    wp.rw1 = rw1; wp.rw2 = rw2w;

    const uint32_t bar_base  = smem_u32(mbars);
    const uint32_t ring_base = smem_u32(wb);
    uint32_t rank;
    asm("mov.u32 %0, %%cluster_ctarank;" : "=r"(rank));

    if (tid == 0) {
        #pragma unroll
        for (int s = 0; s < NSTAGES; s++) {
            mbar_init(bar_base + s * 16, 1);        // full: 1 expect_tx arrive
            mbar_init(bar_base + s * 16 + 8, 4);    // empty: 1 arrive per cluster CTA
        }
    }
    __syncthreads();
    cluster_sync_all();   // barriers visible cluster-wide before any multicast

    if (tid >= NCONS) {
        // ---------------- producer warp ----------------
        if (tid == NCONS) {
            for (int j = 0; j < NT; j++) produce(j, bar_base, ring_base, wp, rank);
        }
    } else {
        // ---------------- consumers (256 threads) ----------------
        for (int i = tid; i < 784; i += NCONS) sx[i] = x[b * 784 + i];
        CONS_SYNC();

        int tn = 0;
        float* ws;

        // enc1: 784 -> 256, leaky_relu (25 tiles)
        {
            float acc = eb1[tid];
            for (int t = 0; t < 25; t++) {
                TILE_BEGIN();
                const int r0 = t * 32, rows = (t < 24) ? 32 : 16;
                #pragma unroll 8
                for (int r = 0; r < rows; r++)
                    acc = fmaf(sx[r0 + r], ws[r * 256 + tid], acc);
                TILE_END();
            }
            h1[tid] = lrelu(acc);
        }
        CONS_SYNC();

        // enc2: 256 -> 256 (8 tiles)
        {
            float acc = eb2[tid];
            for (int t = 0; t < 8; t++) {
                TILE_BEGIN();
                const int r0 = t * 32;
                #pragma unroll 8
                for (int r = 0; r < 32; r++)
                    acc = fmaf(h1[r0 + r], ws[r * 256 + tid], acc);
                TILE_END();
            }
            h2[tid] = lrelu(acc);
        }
        CONS_SYNC();

        // mu: 256 -> 64 (2 tiles, 4-way K split)
        {
            const int g = tid >> 6, l = tid & 63;
            float a = 0.0f;
            for (int t = 0; t < 2; t++) {
                TILE_BEGIN();
                #pragma unroll 8
                for (int i = 0; i < 32; i++) {
                    int kl = g * 32 + i;
                    a = fmaf(h2[t * 128 + kl], ws[kl * 64 + l], a);
                }
                TILE_END();
            }
            red[tid] = a;
        }
        CONS_SYNC();
        if (tid < 64)
            muv[tid] = mub[tid] + ((red[tid] + red[64 + tid]) + (red[128 + tid] + red[192 + tid]));
        CONS_SYNC();

        // logvar: 256 -> 64 (2 tiles)
        {
            const int g = tid >> 6, l = tid & 63;
            float a = 0.0f;
            for (int t = 0; t < 2; t++) {
                TILE_BEGIN();
                #pragma unroll 8
                for (int i = 0; i < 32; i++) {
                    int kl = g * 32 + i;
                    a = fmaf(h2[t * 128 + kl], ws[kl * 64 + l], a);
                }
                TILE_END();
            }
            red[tid] = a;
        }
        CONS_SYNC();
        if (tid < 64) {
            float lvV = lvb[tid] + ((red[tid] + red[64 + tid]) + (red[128 + tid] + red[192 + tid]));
            float m = muv[tid];
            out[OUT_MU + b * 64 + tid] = m;
            out[OUT_LV + b * 64 + tid] = lvV;
            hin[tid] = m + eps[b * 64 + tid] * expf(0.5f * lvV);   // z
        }
        CONS_SYNC();

        // dec1: 64 -> 512, selu (4 tiles)
        {
            float a0 = db1[tid], a1 = db1[tid + 256];
            for (int t = 0; t < 4; t++) {
                TILE_BEGIN();
                const int r0 = t * 16;
                #pragma unroll
                for (int r = 0; r < 16; r++) {
                    float av = hin[r0 + r];
                    a0 = fmaf(av, ws[r * 512 + tid], a0);
                    a1 = fmaf(av, ws[r * 512 + tid + 256], a1);
                }
                TILE_END();
            }
            d1[tid] = seluf(a0); d1[tid + 256] = seluf(a1);
        }
        CONS_SYNC();

        // dec2: 512 -> 512, selu (32 tiles)
        {
            float a0 = db2[tid], a1 = db2[tid + 256];
            for (int t = 0; t < 32; t++) {
                TILE_BEGIN();
                const int r0 = t * 16;
                #pragma unroll
                for (int r = 0; r < 16; r++) {
                    float av = d1[r0 + r];
                    a0 = fmaf(av, ws[r * 512 + tid], a0);
                    a1 = fmaf(av, ws[r * 512 + tid + 256], a1);
                }
                TILE_END();
            }
            d2[tid] = seluf(a0); d2[tid + 256] = seluf(a1);
        }
        CONS_SYNC();

        // coarse cp: 512 -> 28, tanh (2 tiles, 8-way K split)
        {
            const int g = tid >> 5, l = tid & 31;
            float a = 0.0f;
            for (int t = 0; t < 2; t++) {
                TILE_BEGIN();
                if (l < 28) {
                    #pragma unroll 8
                    for (int i = 0; i < 32; i++) {
                        int kl = g * 32 + i;
                        a = fmaf(d2[t * 256 + kl], ws[kl * 28 + l], a);
                    }
                }
                TILE_END();
            }
            red[tid] = a;
        }
        CONS_SYNC();
        if (tid < 28) {
            float s = cpb[tid];
            #pragma unroll
            for (int k = 0; k < 8; k++) s += red[k * 32 + tid];
            hin[64 + tid] = tanhf(s);
        }
        CONS_SYNC();

        // widths: 512 -> 2 (1 tile)
        TILE_BEGIN();
        {
            const int pp = tid >> 7, l = tid & 127;
            float a = 0.0f;
            #pragma unroll
            for (int k = 0; k < 4; k++) { int i = l + k * 128; a = fmaf(d2[i], ws[i * 2 + pp], a); }
            red[tid] = a;
        }
        TILE_END();
        if (tid < 2) {
            const float* rp = &red[tid * 128];
            float s0 = 0, s1 = 0, s2 = 0, s3 = 0;
            #pragma unroll
            for (int j = 0; j < 32; j++) { s0 += rp[j]; s1 += rp[32 + j]; s2 += rp[64 + j]; s3 += rp[96 + j]; }
            float wv = sigm(wdb[tid] + ((s0 + s1) + (s2 + s3))) * 2.0f + 1.0f;
            wa[tid] = wv;
            out[OUT_W + b * 2 + tid] = wv;
        }
        CONS_SYNC();   // protect red[] reads above from alphas' red[] writes

        // alphas: 512 -> 2 (1 tile)
        TILE_BEGIN();
        {
            const int pp = tid >> 7, l = tid & 127;
            float a = 0.0f;
            #pragma unroll
            for (int k = 0; k < 4; k++) { int i = l + k * 128; a = fmaf(d2[i], ws[i * 2 + pp], a); }
            red[tid] = a;
        }
        TILE_END();
        if (tid < 2) {
            const float* rp = &red[tid * 128];
            float s0 = 0, s1 = 0, s2 = 0, s3 = 0;
            #pragma unroll
            for (int j = 0; j < 32; j++) { s0 += rp[j]; s1 += rp[32 + j]; s2 += rp[64 + j]; s3 += rp[96 + j]; }
            float av = sigm(alb[tid] + ((s0 + s1) + (s2 + s3)));
            wa[2 + tid] = av;
            out[OUT_A + b * 2 + tid] = av;
        }
        CONS_SYNC();   // protect red[] reads above from later writes

        // refine1: 92 -> 512, selu (6 tiles)
        {
            float a0 = rb1[tid], a1 = rb1[tid + 256];
            for (int t = 0; t < 6; t++) {
                TILE_BEGIN();
                const int r0 = t * 16, rows = (t < 5) ? 16 : 12;
                #pragma unroll
                for (int r = 0; r < rows; r++) {
                    float av = hin[r0 + r];
                    a0 = fmaf(av, ws[r * 512 + tid], a0);
                    a1 = fmaf(av, ws[r * 512 + tid + 256], a1);
                }
                TILE_END();
            }
            r1[tid] = seluf(a0); r1[tid + 256] = seluf(a1);
        }
        CONS_SYNC();

        // refine2: 512 -> 52 (4 tiles, 4-way K split)
        {
            const int g = tid >> 6, l = tid & 63;
            float a = 0.0f;
            for (int t = 0; t < 4; t++) {
                TILE_BEGIN();
                if (l < 52) {
                    #pragma unroll 8
                    for (int i = 0; i < 32; i++) {
                        int kl = g * 32 + i;
                        a = fmaf(r1[t * 128 + kl], ws[kl * 52 + l], a);
                    }
                }
                TILE_END();
            }
            red[tid] = a;
        }
        CONS_SYNC();
        if (tid < 52) {
            float s = rb2[tid] + ((red[tid] + red[64 + tid]) + (red[128 + tid] + red[192 + tid]));
            pts[tid] = tanhf(s) * SCALEC + HALFC;
        }
        CONS_SYNC();

        // control points out + bezier sample eval
        if (tid < 64) {
            const int p = tid >> 5, rem = tid & 31;
            {
                int s = rem >> 3, k = (rem >> 1) & 3, d = rem & 1;
                out[OUT_CP + b * 64 + tid] = pts[p * 26 + (3 * s + k) * 2 + d];
            }
            const int ss = rem >> 3, ti = rem & 7;
            float t  = (float)ti / 7.0f;
            float mt = 1.0f - t;
            float b0 = mt * mt * mt;
            float b1 = 3.0f * mt * mt * t;
            float b2 = 3.0f * mt * t * t;
            float b3 = t * t * t;
            int base = p * 26 + (3 * ss) * 2;
            float X = b0 * pts[base + 0] + b1 * pts[base + 2] + b2 * pts[base + 4] + b3 * pts[base + 6];
            float Y = b0 * pts[base + 1] + b1 * pts[base + 3] + b2 * pts[base + 5] + b3 * pts[base + 7];
            qx[tid] = X; qy[tid] = Y; qq[tid] = X * X + Y * Y;
        }
        CONS_SYNC();
        if (tid < 64) {
            const int p = tid >> 5, m = tid & 31;
            float y0 = qy[tid];
            float y1 = qy[p * 32 + ((m + 1) & 31)];
            sinv[tid] = __fdiv_rn(1.0f, (y1 - y0) + 1e-8f);
        }
        CONS_SYNC();

        // rasterizer
        for (int px = tid; px < 784; px += NCONS) {
            const int pi = px / 28, pj = px - pi * 28;
            float acc = 0.0f;
            #pragma unroll
            for (int sub = 0; sub < 4; sub++) {
                const float sy  = (float)pi + (0.25f + 0.5f * (float)(sub >> 1));
                const float sxv = (float)pj + (0.25f + 0.5f * (float)(sub & 1));
                const float ssn = sxv * sxv + sy * sy;
                const float nx  = -2.0f * sxv, ny = -2.0f * sy;

                float val = 1.0f;
                #pragma unroll
                for (int p = 0; p < 2; p++) {
                    const int base = p * 32;
                    float mind2 = 3.402823e38f;
                    int nc = 0;
                    float x0 = qx[base], y0 = qy[base];
                    bool c0 = y0 > sy;
                    #pragma unroll 8
                    for (int m = 0; m < 32; m++) {
                        const int mn = base + ((m + 1) & 31);
                        const float x1 = qx[mn], y1 = qy[mn];
                        float v = fmaf(nx, x0, fmaf(ny, y0, qq[base + m] + ssn));
                        mind2 = fminf(mind2, fmaxf(v, 0.0f));
                        const bool c1 = y1 > sy;
                        const float xint = fmaf((sy - y0) * sinv[base + m], x1 - x0, x0);
                        nc += (int)((c0 != c1) && (sxv < xint));
                        x0 = x1; y0 = y1; c0 = c1;
                    }
                    const float dist   = sqrtf(mind2);
                    const float stroke = fminf(fmaxf(fmaf(wa[p], 0.5f, 0.5f) - dist, 0.0f), 1.0f);
                    const float cov    = fmaxf((float)(nc & 1), stroke);
                    val *= 1.0f - wa[2 + p] * cov;
                }
                acc += val;
            }
            out[OUT_R + b * 784 + px] = 1.0f - 0.25f * acc;
        }
    }

    cluster_sync_all();   // no CTA exits while peers might still multicast into it
}

// ---------------------------------------------------------------------------
extern "C" void kernel_launch(void* const* d_in, const int* in_sizes, int n_in,
                              void* d_out, int out_size)
{
    const float* x    = (const float*)d_in[0];
    const float* eps  = (const float*)d_in[1];
    const float* ew1  = (const float*)d_in[2];
    const float* eb1  = (const float*)d_in[3];
    const float* ew2  = (const float*)d_in[4];
    const float* eb2  = (const float*)d_in[5];
    const float* muw  = (const float*)d_in[6];
    const float* mub  = (const float*)d_in[7];
    const float* lvw  = (const float*)d_in[8];
    const float* lvb  = (const float*)d_in[9];
    const float* dw1  = (const float*)d_in[10];
    const float* db1  = (const float*)d_in[11];
    const float* dw2  = (const float*)d_in[12];
    const float* db2  = (const float*)d_in[13];
    const float* cpw  = (const float*)d_in[14];
    const float* cpb  = (const float*)d_in[15];
    const float* rw1  = (const float*)d_in[16];
    const float* rb1  = (const float*)d_in[17];
    const float* rw2  = (const float*)d_in[18];
    const float* rb2  = (const float*)d_in[19];
    const float* wdw  = (const float*)d_in[20];
    const float* wdb  = (const float*)d_in[21];
    const float* alw  = (const float*)d_in[22];
    const float* alb  = (const float*)d_in[23];
    float* out = (float*)d_out;

    const int dyn = NSTAGES * STAGE_FLOATS * 4;   // 196608 bytes
    cudaFuncSetAttribute(fused_kernel, cudaFuncAttributeMaxDynamicSharedMemorySize, dyn);
    fused_kernel<<<BATCH, TPB, dyn>>>(x, eps, ew1, eb1, ew2, eb2, muw, mub, lvw, lvb,
                                      dw1, db1, dw2, db2, cpw, cpb, rw1, rb1, rw2, rb2,
                                      wdw, wdb, alw, alb, out);
}

// round 6
// speedup vs baseline: 3.5243x; 1.1448x over previous
#include <cuda_runtime.h>
#include <math.h>
#include <stdint.h>

// ---------------------------------------------------------------------------
// HierarchicalVAE fused, cluster-4 multicast weight streaming,
// warp-specialized producer + per-warp tile release (no per-tile CTA barrier).
// grid = 128 CTAs (1 per batch element), 32 clusters x 4 CTAs, 288 threads:
//   warps 0-7 (256 thr): consumers - MLP chain + rasterizer
//   warp 8, thread 256:  producer - streams 44 weight tiles through a
//                        3-stage x 64KB smem ring via cp.async.bulk.multicast
// Empty barriers count 32 arrives (8 warps x 4 CTAs): each consumer warp
// releases a slot independently; no bar.sync inside the tile stream.
// ---------------------------------------------------------------------------

#define BATCH 128
#define TPB 288
#define NCONS 256
#define CLUSTER 4
#define NSTAGES 3
#define STAGE_FLOATS 16384           // 64KB
#define STAGE_BYTES  65536
#define NT 44
#define HALFC 14.0f
#define SCALEC 12.0f

#define OUT_R  0
#define OUT_MU (BATCH*784)
#define OUT_LV (OUT_MU + BATCH*64)
#define OUT_CP (OUT_LV + BATCH*64)
#define OUT_W  (OUT_CP + BATCH*64)
#define OUT_A  (OUT_W + BATCH*2)

struct WPtrs {
    const float *ew1, *ew2, *muw, *lvw, *dw1, *dw2, *cpw, *wdw, *alw, *rw1, *rw2;
};

__device__ __forceinline__ uint32_t smem_u32(const void* p) {
    return (uint32_t)__cvta_generic_to_shared(p);
}

__device__ __forceinline__ void mbar_init(uint32_t addr, uint32_t count) {
    asm volatile("mbarrier.init.shared.b64 [%0], %1;" :: "r"(addr), "r"(count) : "memory");
}
__device__ __forceinline__ void mbar_wait(uint32_t addr, uint32_t parity) {
    asm volatile(
        "{\n\t.reg .pred P;\n"
        "W_%=:\n\t"
        "mbarrier.try_wait.parity.acquire.cta.shared::cta.b64 P, [%0], %1, 0x989680;\n\t"
        "@P bra.uni D_%=;\n\t"
        "bra.uni W_%=;\n"
        "D_%=:\n\t}"
        :: "r"(addr), "r"(parity) : "memory");
}
__device__ __forceinline__ void mbar_expect_tx(uint32_t addr, uint32_t bytes) {
    asm volatile("mbarrier.arrive.expect_tx.shared.b64 _, [%0], %1;"
                 :: "r"(addr), "r"(bytes) : "memory");
}
__device__ __forceinline__ void mbar_arrive_rank(uint32_t addr, uint32_t rank) {
    asm volatile(
        "{\n\t.reg .b32 ra;\n\t"
        "mapa.shared::cluster.u32 ra, %0, %1;\n\t"
        "mbarrier.arrive.shared::cluster.b64 _, [ra];\n\t}"
        :: "r"(addr), "r"(rank) : "memory");
}
__device__ __forceinline__ void cluster_sync_all() {
    asm volatile("barrier.cluster.arrive.aligned;" ::: "memory");
    asm volatile("barrier.cluster.wait.aligned;" ::: "memory");
}
__device__ __forceinline__ void bulk_mc(uint32_t dst, const void* src, uint32_t bytes,
                                        uint32_t mbar, uint16_t mask) {
    asm volatile(
        "cp.async.bulk.shared::cluster.global.mbarrier::complete_tx::bytes.multicast::cluster "
        "[%0], [%1], %2, [%3], %4;"
        :: "r"(dst), "l"(src), "r"(bytes), "r"(mbar), "h"(mask) : "memory");
}

__device__ __forceinline__ float seluf(float x) {
    const float sc = 1.0507009873554805f;
    const float al = 1.6732632423543772f;
    return x > 0.0f ? sc * x : sc * al * (expf(x) - 1.0f);
}
__device__ __forceinline__ float lrelu(float x) { return x >= 0.0f ? x : 0.2f * x; }
__device__ __forceinline__ float sigm(float x)  { return 1.0f / (1.0f + expf(-x)); }

// Tile table (44 tiles, 64KB stages):
//  [0,13)  enc1 784x256, 64-row tiles (last 16)
//  [13,17) enc2 256x256, 64-row
//  [17]    muw 256x64 whole (64KB)
//  [18]    lvw 256x64 whole
//  [19,21) dec1 64x512, 32-row
//  [21,37) dec2 512x512, 32-row
//  [37]    cpw 512x28 whole (56KB)
//  [38]    wdw + alw (two 4KB segments; alw at float offset 1024)
//  [39,42) rw1 92x512, 32-row (last 28)
//  [42,44) rw2 512x52, 256-row (52KB)
__device__ __forceinline__ int tile_segs(int n, const WPtrs& p,
                                         const char* srcs[2], uint32_t szs[2]) {
    if (n < 13) { int r0 = n * 64; int rows = (r0 + 64 <= 784) ? 64 : (784 - r0);
                  srcs[0] = (const char*)(p.ew1 + r0 * 256); szs[0] = rows * 1024; return 1; }
    n -= 13;
    if (n < 4)  { srcs[0] = (const char*)(p.ew2 + n * 64 * 256); szs[0] = 65536; return 1; }
    n -= 4;
    if (n == 0) { srcs[0] = (const char*)p.muw; szs[0] = 65536; return 1; } n--;
    if (n == 0) { srcs[0] = (const char*)p.lvw; szs[0] = 65536; return 1; } n--;
    if (n < 2)  { srcs[0] = (const char*)(p.dw1 + n * 32 * 512); szs[0] = 65536; return 1; }
    n -= 2;
    if (n < 16) { srcs[0] = (const char*)(p.dw2 + n * 32 * 512); szs[0] = 65536; return 1; }
    n -= 16;
    if (n == 0) { srcs[0] = (const char*)p.cpw; szs[0] = 57344; return 1; } n--;
    if (n == 0) { srcs[0] = (const char*)p.wdw; szs[0] = 4096;
                  srcs[1] = (const char*)p.alw; szs[1] = 4096; return 2; } n--;
    if (n < 3)  { int r0 = n * 32; int rows = (r0 + 32 <= 92) ? 32 : (92 - r0);
                  srcs[0] = (const char*)(p.rw1 + r0 * 512); szs[0] = rows * 2048; return 1; }
    n -= 3;
    srcs[0] = (const char*)(p.rw2 + n * 256 * 52); szs[0] = 53248; return 1;
}

// producer thread: wait slot empty, expect full tile, multicast this rank's quarter.
__device__ __forceinline__ void produce(int j, uint32_t bar_base, uint32_t ring_base,
                                        const WPtrs& p, uint32_t rank) {
    const int s = j % NSTAGES;
    mbar_wait(bar_base + s * 16 + 8, 1u ^ ((uint32_t)(j / NSTAGES) & 1u));
    const char* srcs[2]; uint32_t szs[2];
    int ns = tile_segs(j, p, srcs, szs);
    uint32_t total = szs[0] + ((ns > 1) ? szs[1] : 0u);
    const uint32_t full = bar_base + s * 16;
    mbar_expect_tx(full, total);
    uint32_t dst = ring_base + s * STAGE_BYTES;
    for (int k = 0; k < ns; k++) {
        uint32_t slice = szs[k] >> 2;   // /CLUSTER
        bulk_mc(dst + rank * slice, srcs[k] + rank * slice, slice, full, 0xF);
        dst += szs[k];
    }
}

#define CONS_SYNC() asm volatile("bar.sync 1, %0;" :: "n"(NCONS) : "memory")

#define TILE_BEGIN() do { \
        mbar_wait(bar_base + (tn % NSTAGES) * 16, (uint32_t)(tn / NSTAGES) & 1u); \
        ws = wb + (tn % NSTAGES) * STAGE_FLOATS; } while (0)

// per-warp release: no CTA barrier; warp's reads ordered by syncwarp + release arrive
#define TILE_END() do { __syncwarp(); \
        if ((tid & 31) == 0) { uint32_t e = bar_base + (tn % NSTAGES) * 16 + 8; \
            mbar_arrive_rank(e, 0); mbar_arrive_rank(e, 1); \
            mbar_arrive_rank(e, 2); mbar_arrive_rank(e, 3); } \
        tn++; } while (0)

__global__ void __launch_bounds__(TPB, 1) __cluster_dims__(CLUSTER, 1, 1)
fused_kernel(
    const float* __restrict__ x,    const float* __restrict__ eps,
    const float* __restrict__ ew1,  const float* __restrict__ eb1,
    const float* __restrict__ ew2,  const float* __restrict__ eb2,
    const float* __restrict__ muw,  const float* __restrict__ mub,
    const float* __restrict__ lvw,  const float* __restrict__ lvb,
    const float* __restrict__ dw1,  const float* __restrict__ db1,
    const float* __restrict__ dw2,  const float* __restrict__ db2,
    const float* __restrict__ cpw,  const float* __restrict__ cpb,
    const float* __restrict__ rw1,  const float* __restrict__ rb1,
    const float* __restrict__ rw2w, const float* __restrict__ rb2,
    const float* __restrict__ wdw,  const float* __restrict__ wdb,
    const float* __restrict__ alw,  const float* __restrict__ alb,
    float* __restrict__ out)
{
    extern __shared__ float wb[];   // NSTAGES * STAGE_FLOATS

    const int b   = blockIdx.x;
    const int tid = threadIdx.x;

    __shared__ alignas(16) unsigned long long mbars[NSTAGES * 2]; // [full,empty] x 3
    __shared__ float sx[784];
    __shared__ float h1[256];
    __shared__ float h2[256];
    __shared__ float muv[64];
    __shared__ float hin[92];       // z (0..63) + tanh coarse (64..91)
    __shared__ float d1[512];
    __shared__ float d2[512];
    __shared__ float r1[512];
    __shared__ float pts[52];
    __shared__ float red[256];
    __shared__ float red2[256];
    __shared__ float qx[64], qy[64], qq[64], sinv[64], wa[4];

    WPtrs wp; wp.ew1 = ew1; wp.ew2 = ew2; wp.muw = muw; wp.lvw = lvw;
    wp.dw1 = dw1; wp.dw2 = dw2; wp.cpw = cpw; wp.wdw = wdw; wp.alw = alw;
    wp.rw1 = rw1; wp.rw2 = rw2w;

    const uint32_t bar_base  = smem_u32(mbars);
    const uint32_t ring_base = smem_u32(wb);
    uint32_t rank;
    asm("mov.u32 %0, %%cluster_ctarank;" : "=r"(rank));

    if (tid == 0) {
        #pragma unroll
        for (int s = 0; s < NSTAGES; s++) {
            mbar_init(bar_base + s * 16, 1);         // full: 1 expect_tx arrive
            mbar_init(bar_base + s * 16 + 8, 32);    // empty: 8 warps x 4 CTAs
        }
    }
    __syncthreads();
    cluster_sync_all();   // barriers visible cluster-wide before any multicast

    if (tid >= NCONS) {
        // ---------------- producer warp ----------------
        if (tid == NCONS) {
            for (int j = 0; j < NT; j++) produce(j, bar_base, ring_base, wp, rank);
        }
    } else {
        // ---------------- consumers (256 threads, 8 warps) ----------------
        for (int i = tid; i < 784; i += NCONS) sx[i] = x[b * 784 + i];
        CONS_SYNC();

        int tn = 0;
        float* ws;

        // enc1: 784 -> 256, leaky_relu (13 tiles)
        {
            float acc = eb1[tid];
            for (int t = 0; t < 13; t++) {
                TILE_BEGIN();
                const int r0 = t * 64, rows = (t < 12) ? 64 : 16;
                #pragma unroll 8
                for (int r = 0; r < rows; r++)
                    acc = fmaf(sx[r0 + r], ws[r * 256 + tid], acc);
                TILE_END();
            }
            h1[tid] = lrelu(acc);
        }
        CONS_SYNC();

        // enc2: 256 -> 256 (4 tiles)
        {
            float acc = eb2[tid];
            for (int t = 0; t < 4; t++) {
                TILE_BEGIN();
                const int r0 = t * 64;
                #pragma unroll 8
                for (int r = 0; r < 64; r++)
                    acc = fmaf(h1[r0 + r], ws[r * 256 + tid], acc);
                TILE_END();
            }
            h2[tid] = lrelu(acc);
        }
        CONS_SYNC();

        // mu: 256 -> 64 (1 tile, 4-way K split: group g = rows g*64..g*64+63)
        {
            const int g = tid >> 6, l = tid & 63;
            TILE_BEGIN();
            float a = 0.0f;
            #pragma unroll 8
            for (int i = 0; i < 64; i++) {
                int kl = g * 64 + i;
                a = fmaf(h2[kl], ws[kl * 64 + l], a);
            }
            red[tid] = a;
            TILE_END();
        }
        CONS_SYNC();
        if (tid < 64)
            muv[tid] = mub[tid] + ((red[tid] + red[64 + tid]) + (red[128 + tid] + red[192 + tid]));
        CONS_SYNC();

        // logvar: 256 -> 64 (1 tile)
        {
            const int g = tid >> 6, l = tid & 63;
            TILE_BEGIN();
            float a = 0.0f;
            #pragma unroll 8
            for (int i = 0; i < 64; i++) {
                int kl = g * 64 + i;
                a = fmaf(h2[kl], ws[kl * 64 + l], a);
            }
            red[tid] = a;
            TILE_END();
        }
        CONS_SYNC();
        if (tid < 64) {
            float lvV = lvb[tid] + ((red[tid] + red[64 + tid]) + (red[128 + tid] + red[192 + tid]));
            float m = muv[tid];
            out[OUT_MU + b * 64 + tid] = m;
            out[OUT_LV + b * 64 + tid] = lvV;
            hin[tid] = m + eps[b * 64 + tid] * expf(0.5f * lvV);   // z
        }
        CONS_SYNC();

        // dec1: 64 -> 512, selu (2 tiles of 32 rows)
        {
            float a0 = db1[tid], a1 = db1[tid + 256];
            for (int t = 0; t < 2; t++) {
                TILE_BEGIN();
                const int r0 = t * 32;
                #pragma unroll 8
                for (int r = 0; r < 32; r++) {
                    float av = hin[r0 + r];
                    a0 = fmaf(av, ws[r * 512 + tid], a0);
                    a1 = fmaf(av, ws[r * 512 + tid + 256], a1);
                }
                TILE_END();
            }
            d1[tid] = seluf(a0); d1[tid + 256] = seluf(a1);
        }
        CONS_SYNC();

        // dec2: 512 -> 512, selu (16 tiles of 32 rows)
        {
            float a0 = db2[tid], a1 = db2[tid + 256];
            for (int t = 0; t < 16; t++) {
                TILE_BEGIN();
                const int r0 = t * 32;
                #pragma unroll 8
                for (int r = 0; r < 32; r++) {
                    float av = d1[r0 + r];
                    a0 = fmaf(av, ws[r * 512 + tid], a0);
                    a1 = fmaf(av, ws[r * 512 + tid + 256], a1);
                }
                TILE_END();
            }
            d2[tid] = seluf(a0); d2[tid + 256] = seluf(a1);
        }
        CONS_SYNC();

        // coarse cp: 512 -> 28, tanh (1 tile, 8-way K split: rows g*64..g*64+63)
        {
            const int g = tid >> 5, l = tid & 31;
            TILE_BEGIN();
            float a = 0.0f;
            if (l < 28) {
                #pragma unroll 8
                for (int i = 0; i < 64; i++) {
                    int kl = g * 64 + i;
                    a = fmaf(d2[kl], ws[kl * 28 + l], a);
                }
            }
            red[tid] = a;
            TILE_END();
        }
        CONS_SYNC();
        if (tid < 28) {
            float s = cpb[tid];
            #pragma unroll
            for (int k = 0; k < 8; k++) s += red[k * 32 + tid];
            hin[64 + tid] = tanhf(s);
        }
        CONS_SYNC();

        // widths + alphas: 512 -> 2 each (1 fused tile; alw at float offset 1024)
        {
            const int pp = tid >> 7, l = tid & 127;
            TILE_BEGIN();
            float aw = 0.0f, aa = 0.0f;
            #pragma unroll
            for (int k = 0; k < 4; k++) {
                int i = l + k * 128;
                aw = fmaf(d2[i], ws[i * 2 + pp], aw);
                aa = fmaf(d2[i], ws[1024 + i * 2 + pp], aa);
            }
            red[tid] = aw; red2[tid] = aa;
            TILE_END();
        }
        CONS_SYNC();
        if (tid < 2) {
            const float* rp = &red[tid * 128];
            float s0 = 0, s1 = 0, s2 = 0, s3 = 0;
            #pragma unroll
            for (int j = 0; j < 32; j++) { s0 += rp[j]; s1 += rp[32 + j]; s2 += rp[64 + j]; s3 += rp[96 + j]; }
            float wv = sigm(wdb[tid] + ((s0 + s1) + (s2 + s3))) * 2.0f + 1.0f;
            wa[tid] = wv;
            out[OUT_W + b * 2 + tid] = wv;
        } else if (tid >= 32 && tid < 34) {
            const int pA = tid - 32;
            const float* rp = &red2[pA * 128];
            float s0 = 0, s1 = 0, s2 = 0, s3 = 0;
            #pragma unroll
            for (int j = 0; j < 32; j++) { s0 += rp[j]; s1 += rp[32 + j]; s2 += rp[64 + j]; s3 += rp[96 + j]; }
            float av = sigm(alb[pA] + ((s0 + s1) + (s2 + s3)));
            wa[2 + pA] = av;
            out[OUT_A + b * 2 + pA] = av;
        }
        CONS_SYNC();

        // refine1: 92 -> 512, selu (3 tiles of 32 rows, last 28)
        {
            float a0 = rb1[tid], a1 = rb1[tid + 256];
            for (int t = 0; t < 3; t++) {
                TILE_BEGIN();
                const int r0 = t * 32, rows = (t < 2) ? 32 : 28;
                #pragma unroll 8
                for (int r = 0; r < rows; r++) {
                    float av = hin[r0 + r];
                    a0 = fmaf(av, ws[r * 512 + tid], a0);
                    a1 = fmaf(av, ws[r * 512 + tid + 256], a1);
                }
                TILE_END();
            }
            r1[tid] = seluf(a0); r1[tid + 256] = seluf(a1);
        }
        CONS_SYNC();

        // refine2: 512 -> 52 (2 tiles of 256 rows, 4-way K split)
        {
            const int g = tid >> 6, l = tid & 63;
            float a = 0.0f;
            for (int t = 0; t < 2; t++) {
                TILE_BEGIN();
                if (l < 52) {
                    #pragma unroll 8
                    for (int i = 0; i < 64; i++) {
                        int kl = g * 64 + i;
                        a = fmaf(r1[t * 256 + kl], ws[kl * 52 + l], a);
                    }
                }
                TILE_END();
            }
            red[tid] = a;
        }
        CONS_SYNC();
        if (tid < 52) {
            float s = rb2[tid] + ((red[tid] + red[64 + tid]) + (red[128 + tid] + red[192 + tid]));
            pts[tid] = tanhf(s) * SCALEC + HALFC;
        }
        CONS_SYNC();

        // control points out + bezier sample eval
        if (tid < 64) {
            const int p = tid >> 5, rem = tid & 31;
            {
                int s = rem >> 3, k = (rem >> 1) & 3, d = rem & 1;
                out[OUT_CP + b * 64 + tid] = pts[p * 26 + (3 * s + k) * 2 + d];
            }
            const int ss = rem >> 3, ti = rem & 7;
            float t  = (float)ti / 7.0f;
            float mt = 1.0f - t;
            float b0 = mt * mt * mt;
            float b1 = 3.0f * mt * mt * t;
            float b2 = 3.0f * mt * t * t;
            float b3 = t * t * t;
            int base = p * 26 + (3 * ss) * 2;
            float X = b0 * pts[base + 0] + b1 * pts[base + 2] + b2 * pts[base + 4] + b3 * pts[base + 6];
            float Y = b0 * pts[base + 1] + b1 * pts[base + 3] + b2 * pts[base + 5] + b3 * pts[base + 7];
            qx[tid] = X; qy[tid] = Y; qq[tid] = X * X + Y * Y;
        }
        CONS_SYNC();
        if (tid < 64) {
            const int p = tid >> 5, m = tid & 31;
            float y0 = qy[tid];
            float y1 = qy[p * 32 + ((m + 1) & 31)];
            sinv[tid] = __fdiv_rn(1.0f, (y1 - y0) + 1e-8f);
        }
        CONS_SYNC();

        // rasterizer
        for (int px = tid; px < 784; px += NCONS) {
            const int pi = px / 28, pj = px - pi * 28;
            float acc = 0.0f;
            #pragma unroll
            for (int sub = 0; sub < 4; sub++) {
                const float sy  = (float)pi + (0.25f + 0.5f * (float)(sub >> 1));
                const float sxv = (float)pj + (0.25f + 0.5f * (float)(sub & 1));
                const float ssn = sxv * sxv + sy * sy;
                const float nx  = -2.0f * sxv, ny = -2.0f * sy;

                float val = 1.0f;
                #pragma unroll
                for (int p = 0; p < 2; p++) {
                    const int base = p * 32;
                    float mind2 = 3.402823e38f;
                    int nc = 0;
                    float x0 = qx[base], y0 = qy[base];
                    bool c0 = y0 > sy;
                    #pragma unroll 8
                    for (int m = 0; m < 32; m++) {
                        const int mn = base + ((m + 1) & 31);
                        const float x1 = qx[mn], y1 = qy[mn];
                        float v = fmaf(nx, x0, fmaf(ny, y0, qq[base + m] + ssn));
                        mind2 = fminf(mind2, fmaxf(v, 0.0f));
                        const bool c1 = y1 > sy;
                        const float xint = fmaf((sy - y0) * sinv[base + m], x1 - x0, x0);
                        nc += (int)((c0 != c1) && (sxv < xint));
                        x0 = x1; y0 = y1; c0 = c1;
                    }
                    const float dist   = sqrtf(mind2);
                    const float stroke = fminf(fmaxf(fmaf(wa[p], 0.5f, 0.5f) - dist, 0.0f), 1.0f);
                    const float cov    = fmaxf((float)(nc & 1), stroke);
                    val *= 1.0f - wa[2 + p] * cov;
                }
                acc += val;
            }
            out[OUT_R + b * 784 + px] = 1.0f - 0.25f * acc;
        }
    }

    cluster_sync_all();   // no CTA exits while peers might still multicast into it
}

// ---------------------------------------------------------------------------
extern "C" void kernel_launch(void* const* d_in, const int* in_sizes, int n_in,
                              void* d_out, int out_size)
{
    const float* x    = (const float*)d_in[0];
    const float* eps  = (const float*)d_in[1];
    const float* ew1  = (const float*)d_in[2];
    const float* eb1  = (const float*)d_in[3];
    const float* ew2  = (const float*)d_in[4];
    const float* eb2  = (const float*)d_in[5];
    const float* muw  = (const float*)d_in[6];
    const float* mub  = (const float*)d_in[7];
    const float* lvw  = (const float*)d_in[8];
    const float* lvb  = (const float*)d_in[9];
    const float* dw1  = (const float*)d_in[10];
    const float* db1  = (const float*)d_in[11];
    const float* dw2  = (const float*)d_in[12];
    const float* db2  = (const float*)d_in[13];
    const float* cpw  = (const float*)d_in[14];
    const float* cpb  = (const float*)d_in[15];
    const float* rw1  = (const float*)d_in[16];
    const float* rb1  = (const float*)d_in[17];
    const float* rw2  = (const float*)d_in[18];
    const float* rb2  = (const float*)d_in[19];
    const float* wdw  = (const float*)d_in[20];
    const float* wdb  = (const float*)d_in[21];
    const float* alw  = (const float*)d_in[22];
    const float* alb  = (const float*)d_in[23];
    float* out = (float*)d_out;

    const int dyn = NSTAGES * STAGE_BYTES;   // 196608 bytes
    cudaFuncSetAttribute(fused_kernel, cudaFuncAttributeMaxDynamicSharedMemorySize, dyn);
    fused_kernel<<<BATCH, TPB, dyn>>>(x, eps, ew1, eb1, ew2, eb2, muw, mub, lvw, lvb,
                                      dw1, db1, dw2, db2, cpw, cpb, rw1, rb1, rw2, rb2,
                                      wdw, wdb, alw, alb, out);
}

// round 7
// speedup vs baseline: 4.0197x; 1.1405x over previous
#include <cuda_runtime.h>
#include <math.h>
#include <stdint.h>

// ---------------------------------------------------------------------------
// HierarchicalVAE fused: cluster-4 multicast weight streaming, warp-specialized
// producer, 512 consumer threads, float4-packed raster with subsample-inner loop.
// grid = 128 CTAs (1 per batch), 32 clusters x 4 CTAs, 544 threads:
//   warps 0-15 (512 thr): consumers - MLP chain + rasterizer
//   warp 16, thread 512:  producer - 44 weight tiles, 3-stage x 64KB ring
// Per-warp slot release: empty mbarrier counts 64 (16 warps x 4 CTAs).
// ---------------------------------------------------------------------------

#define BATCH 128
#define TPB 544
#define NC 512
#define CLUSTER 4
#define NSTAGES 3
#define STAGE_FLOATS 16384           // 64KB
#define STAGE_BYTES  65536
#define NT 44
#define HALFC 14.0f
#define SCALEC 12.0f

#define OUT_R  0
#define OUT_MU (BATCH*784)
#define OUT_LV (OUT_MU + BATCH*64)
#define OUT_CP (OUT_LV + BATCH*64)
#define OUT_W  (OUT_CP + BATCH*64)
#define OUT_A  (OUT_W + BATCH*2)

struct WPtrs {
    const float *ew1, *ew2, *muw, *lvw, *dw1, *dw2, *cpw, *wdw, *alw, *rw1, *rw2;
};

__device__ __forceinline__ uint32_t smem_u32(const void* p) {
    return (uint32_t)__cvta_generic_to_shared(p);
}
__device__ __forceinline__ void mbar_init(uint32_t addr, uint32_t count) {
    asm volatile("mbarrier.init.shared.b64 [%0], %1;" :: "r"(addr), "r"(count) : "memory");
}
__device__ __forceinline__ void mbar_wait(uint32_t addr, uint32_t parity) {
    asm volatile(
        "{\n\t.reg .pred P;\n"
        "W_%=:\n\t"
        "mbarrier.try_wait.parity.acquire.cta.shared::cta.b64 P, [%0], %1, 0x989680;\n\t"
        "@P bra.uni D_%=;\n\t"
        "bra.uni W_%=;\n"
        "D_%=:\n\t}"
        :: "r"(addr), "r"(parity) : "memory");
}
__device__ __forceinline__ void mbar_expect_tx(uint32_t addr, uint32_t bytes) {
    asm volatile("mbarrier.arrive.expect_tx.shared.b64 _, [%0], %1;"
                 :: "r"(addr), "r"(bytes) : "memory");
}
__device__ __forceinline__ void mbar_arrive_rank(uint32_t addr, uint32_t rank) {
    asm volatile(
        "{\n\t.reg .b32 ra;\n\t"
        "mapa.shared::cluster.u32 ra, %0, %1;\n\t"
        "mbarrier.arrive.shared::cluster.b64 _, [ra];\n\t}"
        :: "r"(addr), "r"(rank) : "memory");
}
__device__ __forceinline__ void cluster_sync_all() {
    asm volatile("barrier.cluster.arrive.aligned;" ::: "memory");
    asm volatile("barrier.cluster.wait.aligned;" ::: "memory");
}
__device__ __forceinline__ void bulk_mc(uint32_t dst, const void* src, uint32_t bytes,
                                        uint32_t mbar, uint16_t mask) {
    asm volatile(
        "cp.async.bulk.shared::cluster.global.mbarrier::complete_tx::bytes.multicast::cluster "
        "[%0], [%1], %2, [%3], %4;"
        :: "r"(dst), "l"(src), "r"(bytes), "r"(mbar), "h"(mask) : "memory");
}

__device__ __forceinline__ float seluf(float x) {
    const float sc = 1.0507009873554805f;
    const float al = 1.6732632423543772f;
    return x > 0.0f ? sc * x : sc * al * (expf(x) - 1.0f);
}
__device__ __forceinline__ float lrelu(float x) { return x >= 0.0f ? x : 0.2f * x; }
__device__ __forceinline__ float sigm(float x)  { return 1.0f / (1.0f + expf(-x)); }

// Tile table (44 tiles, 64KB stages) — identical to R6.
__device__ __forceinline__ int tile_segs(int n, const WPtrs& p,
                                         const char* srcs[2], uint32_t szs[2]) {
    if (n < 13) { int r0 = n * 64; int rows = (r0 + 64 <= 784) ? 64 : (784 - r0);
                  srcs[0] = (const char*)(p.ew1 + r0 * 256); szs[0] = rows * 1024; return 1; }
    n -= 13;
    if (n < 4)  { srcs[0] = (const char*)(p.ew2 + n * 64 * 256); szs[0] = 65536; return 1; }
    n -= 4;
    if (n == 0) { srcs[0] = (const char*)p.muw; szs[0] = 65536; return 1; } n--;
    if (n == 0) { srcs[0] = (const char*)p.lvw; szs[0] = 65536; return 1; } n--;
    if (n < 2)  { srcs[0] = (const char*)(p.dw1 + n * 32 * 512); szs[0] = 65536; return 1; }
    n -= 2;
    if (n < 16) { srcs[0] = (const char*)(p.dw2 + n * 32 * 512); szs[0] = 65536; return 1; }
    n -= 16;
    if (n == 0) { srcs[0] = (const char*)p.cpw; szs[0] = 57344; return 1; } n--;
    if (n == 0) { srcs[0] = (const char*)p.wdw; szs[0] = 4096;
                  srcs[1] = (const char*)p.alw; szs[1] = 4096; return 2; } n--;
    if (n < 3)  { int r0 = n * 32; int rows = (r0 + 32 <= 92) ? 32 : (92 - r0);
                  srcs[0] = (const char*)(p.rw1 + r0 * 512); szs[0] = rows * 2048; return 1; }
    n -= 3;
    srcs[0] = (const char*)(p.rw2 + n * 256 * 52); szs[0] = 53248; return 1;
}

__device__ __forceinline__ void produce(int j, uint32_t bar_base, uint32_t ring_base,
                                        const WPtrs& p, uint32_t rank) {
    const int s = j % NSTAGES;
    mbar_wait(bar_base + s * 16 + 8, 1u ^ ((uint32_t)(j / NSTAGES) & 1u));
    const char* srcs[2]; uint32_t szs[2];
    int ns = tile_segs(j, p, srcs, szs);
    uint32_t total = szs[0] + ((ns > 1) ? szs[1] : 0u);
    const uint32_t full = bar_base + s * 16;
    mbar_expect_tx(full, total);
    uint32_t dst = ring_base + s * STAGE_BYTES;
    for (int k = 0; k < ns; k++) {
        uint32_t slice = szs[k] >> 2;   // /CLUSTER
        bulk_mc(dst + rank * slice, srcs[k] + rank * slice, slice, full, 0xF);
        dst += szs[k];
    }
}

#define CONS_SYNC() asm volatile("bar.sync 1, %0;" :: "n"(NC) : "memory")

#define TILE_BEGIN() do { \
        mbar_wait(bar_base + (tn % NSTAGES) * 16, (uint32_t)(tn / NSTAGES) & 1u); \
        ws = wb + (tn % NSTAGES) * STAGE_FLOATS; } while (0)

#define TILE_END() do { __syncwarp(); \
        if ((tid & 31) == 0) { uint32_t e = bar_base + (tn % NSTAGES) * 16 + 8; \
            mbar_arrive_rank(e, 0); mbar_arrive_rank(e, 1); \
            mbar_arrive_rank(e, 2); mbar_arrive_rank(e, 3); } \
        tn++; } while (0)

__global__ void __launch_bounds__(TPB, 1) __cluster_dims__(CLUSTER, 1, 1)
fused_kernel(
    const float* __restrict__ x,    const float* __restrict__ eps,
    const float* __restrict__ ew1,  const float* __restrict__ eb1,
    const float* __restrict__ ew2,  const float* __restrict__ eb2,
    const float* __restrict__ muw,  const float* __restrict__ mub,
    const float* __restrict__ lvw,  const float* __restrict__ lvb,
    const float* __restrict__ dw1,  const float* __restrict__ db1,
    const float* __restrict__ dw2,  const float* __restrict__ db2,
    const float* __restrict__ cpw,  const float* __restrict__ cpb,
    const float* __restrict__ rw1,  const float* __restrict__ rb1,
    const float* __restrict__ rw2w, const float* __restrict__ rb2,
    const float* __restrict__ wdw,  const float* __restrict__ wdb,
    const float* __restrict__ alw,  const float* __restrict__ alb,
    float* __restrict__ out)
{
    extern __shared__ float wb[];   // NSTAGES * STAGE_FLOATS

    const int b   = blockIdx.x;
    const int tid = threadIdx.x;

    __shared__ alignas(16) unsigned long long mbars[NSTAGES * 2];
    __shared__ float sx[784];
    __shared__ float h1[256];
    __shared__ float h2[256];
    __shared__ float muv[64];
    __shared__ float hin[92];
    __shared__ float d1[512];
    __shared__ float d2[512];
    __shared__ float r1[512];
    __shared__ float pts[52];
    __shared__ float red[NC];
    __shared__ float red2[NC];
    __shared__ float qx[64], qy[64], wa[4];
    __shared__ alignas(16) float4 pt4[64];   // (x, y, |q|^2, 1/dy)

    WPtrs wp; wp.ew1 = ew1; wp.ew2 = ew2; wp.muw = muw; wp.lvw = lvw;
    wp.dw1 = dw1; wp.dw2 = dw2; wp.cpw = cpw; wp.wdw = wdw; wp.alw = alw;
    wp.rw1 = rw1; wp.rw2 = rw2w;

    const uint32_t bar_base  = smem_u32(mbars);
    const uint32_t ring_base = smem_u32(wb);
    uint32_t rank;
    asm("mov.u32 %0, %%cluster_ctarank;" : "=r"(rank));

    if (tid == 0) {
        #pragma unroll
        for (int s = 0; s < NSTAGES; s++) {
            mbar_init(bar_base + s * 16, 1);         // full: 1 expect_tx arrive
            mbar_init(bar_base + s * 16 + 8, 64);    // empty: 16 warps x 4 CTAs
        }
    }
    __syncthreads();
    cluster_sync_all();

    if (tid >= NC) {
        // ---------------- producer warp ----------------
        if (tid == NC) {
            for (int j = 0; j < NT; j++) produce(j, bar_base, ring_base, wp, rank);
        }
    } else {
        // ---------------- consumers (512 threads, 16 warps) ----------------
        for (int i = tid; i < 784; i += NC) sx[i] = x[b * 784 + i];
        CONS_SYNC();

        int tn = 0;
        float* ws;

        // enc1: 784 -> 256 (13 tiles), 2-way K split (groups of 256 threads)
        {
            const int g = tid >> 8, o = tid & 255;
            float acc = (g == 0) ? eb1[o] : 0.0f;
            for (int t = 0; t < 13; t++) {
                TILE_BEGIN();
                const int rows = (t < 12) ? 64 : 16, half = rows >> 1;
                const int r0 = g * half, gr = t * 64 + r0;
                #pragma unroll 8
                for (int r = 0; r < half; r++)
                    acc = fmaf(sx[gr + r], ws[(r0 + r) * 256 + o], acc);
                TILE_END();
            }
            red[tid] = acc;
        }
        CONS_SYNC();
        if (tid < 256) h1[tid] = lrelu(red[tid] + red[256 + tid]);
        CONS_SYNC();

        // enc2: 256 -> 256 (4 tiles), 2-way K split
        {
            const int g = tid >> 8, o = tid & 255;
            float acc = (g == 0) ? eb2[o] : 0.0f;
            for (int t = 0; t < 4; t++) {
                TILE_BEGIN();
                const int r0 = g * 32, gr = t * 64 + r0;
                #pragma unroll 8
                for (int r = 0; r < 32; r++)
                    acc = fmaf(h1[gr + r], ws[(r0 + r) * 256 + o], acc);
                TILE_END();
            }
            red[tid] = acc;
        }
        CONS_SYNC();
        if (tid < 256) h2[tid] = lrelu(red[tid] + red[256 + tid]);
        CONS_SYNC();

        // mu: 256 -> 64 (1 tile), 8-way K split
        {
            const int g = tid >> 6, l = tid & 63;
            TILE_BEGIN();
            float a = 0.0f;
            #pragma unroll 8
            for (int i = 0; i < 32; i++) {
                int kl = g * 32 + i;
                a = fmaf(h2[kl], ws[kl * 64 + l], a);
            }
            red[tid] = a;
            TILE_END();
        }
        CONS_SYNC();
        if (tid < 64) {
            float s = mub[tid];
            #pragma unroll
            for (int k = 0; k < 8; k++) s += red[k * 64 + tid];
            muv[tid] = s;
        }
        CONS_SYNC();

        // logvar: 256 -> 64 (1 tile), 8-way K split
        {
            const int g = tid >> 6, l = tid & 63;
            TILE_BEGIN();
            float a = 0.0f;
            #pragma unroll 8
            for (int i = 0; i < 32; i++) {
                int kl = g * 32 + i;
                a = fmaf(h2[kl], ws[kl * 64 + l], a);
            }
            red[tid] = a;
            TILE_END();
        }
        CONS_SYNC();
        if (tid < 64) {
            float lvV = lvb[tid];
            #pragma unroll
            for (int k = 0; k < 8; k++) lvV += red[k * 64 + tid];
            float m = muv[tid];
            out[OUT_MU + b * 64 + tid] = m;
            out[OUT_LV + b * 64 + tid] = lvV;
            hin[tid] = m + eps[b * 64 + tid] * expf(0.5f * lvV);
        }
        CONS_SYNC();

        // dec1: 64 -> 512 (2 tiles of 32 rows), 1 output/thread
        {
            float a = db1[tid];
            for (int t = 0; t < 2; t++) {
                TILE_BEGIN();
                const int r0 = t * 32;
                #pragma unroll 8
                for (int r = 0; r < 32; r++)
                    a = fmaf(hin[r0 + r], ws[r * 512 + tid], a);
                TILE_END();
            }
            d1[tid] = seluf(a);
        }
        CONS_SYNC();

        // dec2: 512 -> 512 (16 tiles of 32 rows), 1 output/thread
        {
            float a = db2[tid];
            for (int t = 0; t < 16; t++) {
                TILE_BEGIN();
                const int r0 = t * 32;
                #pragma unroll 8
                for (int r = 0; r < 32; r++)
                    a = fmaf(d1[r0 + r], ws[r * 512 + tid], a);
                TILE_END();
            }
            d2[tid] = seluf(a);
        }
        CONS_SYNC();

        // coarse cp: 512 -> 28 (1 tile), 16-way K split
        {
            const int g = tid >> 5, l = tid & 31;
            TILE_BEGIN();
            float a = 0.0f;
            if (l < 28) {
                #pragma unroll 8
                for (int i = 0; i < 32; i++) {
                    int kl = g * 32 + i;
                    a = fmaf(d2[kl], ws[kl * 28 + l], a);
                }
            }
            red[tid] = a;
            TILE_END();
        }
        CONS_SYNC();
        if (tid < 28) {
            float s = cpb[tid];
            #pragma unroll
            for (int k = 0; k < 16; k++) s += red[k * 32 + tid];
            hin[64 + tid] = tanhf(s);
        }
        CONS_SYNC();

        // widths + alphas: 512 -> 2 each (1 fused tile; alw at float offset 1024)
        {
            const int pp = tid >> 8, l = tid & 255;
            TILE_BEGIN();
            float aw = fmaf(d2[l], ws[l * 2 + pp], 0.0f);
            aw = fmaf(d2[l + 256], ws[(l + 256) * 2 + pp], aw);
            float aa = fmaf(d2[l], ws[1024 + l * 2 + pp], 0.0f);
            aa = fmaf(d2[l + 256], ws[1024 + (l + 256) * 2 + pp], aa);
            red[tid] = aw; red2[tid] = aa;
            TILE_END();
        }
        CONS_SYNC();
        if (tid < 2) {
            const float* rp = &red[tid * 256];
            float s0 = 0, s1 = 0, s2 = 0, s3 = 0;
            #pragma unroll
            for (int j = 0; j < 64; j++) { s0 += rp[j]; s1 += rp[64 + j]; s2 += rp[128 + j]; s3 += rp[192 + j]; }
            float wv = sigm(wdb[tid] + ((s0 + s1) + (s2 + s3))) * 2.0f + 1.0f;
            wa[tid] = wv;
            out[OUT_W + b * 2 + tid] = wv;
        } else if (tid >= 32 && tid < 34) {
            const int pA = tid - 32;
            const float* rp = &red2[pA * 256];
            float s0 = 0, s1 = 0, s2 = 0, s3 = 0;
            #pragma unroll
            for (int j = 0; j < 64; j++) { s0 += rp[j]; s1 += rp[64 + j]; s2 += rp[128 + j]; s3 += rp[192 + j]; }
            float av = sigm(alb[pA] + ((s0 + s1) + (s2 + s3)));
            wa[2 + pA] = av;
            out[OUT_A + b * 2 + pA] = av;
        }
        CONS_SYNC();

        // refine1: 92 -> 512 (3 tiles), 1 output/thread
        {
            float a = rb1[tid];
            for (int t = 0; t < 3; t++) {
                TILE_BEGIN();
                const int r0 = t * 32, rows = (t < 2) ? 32 : 28;
                #pragma unroll 8
                for (int r = 0; r < rows; r++)
                    a = fmaf(hin[r0 + r], ws[r * 512 + tid], a);
                TILE_END();
            }
            r1[tid] = seluf(a);
        }
        CONS_SYNC();

        // refine2: 512 -> 52 (2 tiles of 256 rows), 8-way K split
        {
            const int g = tid >> 6, l = tid & 63;
            float a = 0.0f;
            for (int t = 0; t < 2; t++) {
                TILE_BEGIN();
                if (l < 52) {
                    #pragma unroll 8
                    for (int i = 0; i < 32; i++) {
                        int kl = g * 32 + i;
                        a = fmaf(r1[t * 256 + kl], ws[kl * 52 + l], a);
                    }
                }
                TILE_END();
            }
            red[tid] = a;
        }
        CONS_SYNC();
        if (tid < 52) {
            float s = rb2[tid];
            #pragma unroll
            for (int k = 0; k < 8; k++) s += red[k * 64 + tid];
            pts[tid] = tanhf(s) * SCALEC + HALFC;
        }
        CONS_SYNC();

        // control points out + bezier sample eval
        if (tid < 64) {
            const int p = tid >> 5, rem = tid & 31;
            {
                int s = rem >> 3, k = (rem >> 1) & 3, d = rem & 1;
                out[OUT_CP + b * 64 + tid] = pts[p * 26 + (3 * s + k) * 2 + d];
            }
            const int ss = rem >> 3, ti = rem & 7;
            float t  = (float)ti / 7.0f;
            float mt = 1.0f - t;
            float b0 = mt * mt * mt;
            float b1 = 3.0f * mt * mt * t;
            float b2 = 3.0f * mt * t * t;
            float b3 = t * t * t;
            int base = p * 26 + (3 * ss) * 2;
            float X = b0 * pts[base + 0] + b1 * pts[base + 2] + b2 * pts[base + 4] + b3 * pts[base + 6];
            float Y = b0 * pts[base + 1] + b1 * pts[base + 3] + b2 * pts[base + 5] + b3 * pts[base + 7];
            qx[tid] = X; qy[tid] = Y;
        }
        CONS_SYNC();
        if (tid < 64) {
            const int p = tid >> 5, m = tid & 31;
            float X = qx[tid], Y = qy[tid];
            float y1 = qy[p * 32 + ((m + 1) & 31)];
            float si = __fdiv_rn(1.0f, (y1 - Y) + 1e-8f);
            pt4[tid] = make_float4(X, Y, X * X + Y * Y, si);
        }
        CONS_SYNC();

        // rasterizer: float4 point loads, 4 AA subsamples inner
        for (int px = tid; px < 784; px += NC) {
            const int pi = px / 28, pj = px - pi * 28;
            float syv[4], sxv[4], nxv[4], nyv[4], ssn[4], val[4];
            #pragma unroll
            for (int s = 0; s < 4; s++) {
                syv[s] = (float)pi + (0.25f + 0.5f * (float)(s >> 1));
                sxv[s] = (float)pj + (0.25f + 0.5f * (float)(s & 1));
                nxv[s] = -2.0f * sxv[s];
                nyv[s] = -2.0f * syv[s];
                ssn[s] = sxv[s] * sxv[s] + syv[s] * syv[s];
                val[s] = 1.0f;
            }
            #pragma unroll
            for (int p = 0; p < 2; p++) {
                const int base = p * 32;
                float mind2[4]; int nc[4]; bool c0[4];
                float4 e = pt4[base];
                #pragma unroll
                for (int s = 0; s < 4; s++) {
                    mind2[s] = 3.402823e38f; nc[s] = 0; c0[s] = e.y > syv[s];
                }
                #pragma unroll 8
                for (int m = 0; m < 32; m++) {
                    const float4 e1 = pt4[base + ((m + 1) & 31)];
                    const float dx = e1.x - e.x;
                    #pragma unroll
                    for (int s = 0; s < 4; s++) {
                        float v = fmaf(nxv[s], e.x, fmaf(nyv[s], e.y, e.z + ssn[s]));
                        mind2[s] = fminf(mind2[s], fmaxf(v, 0.0f));
                        const bool c1 = e1.y > syv[s];
                        const float xint = fmaf((syv[s] - e.y) * e.w, dx, e.x);
                        nc[s] += (int)((c0[s] != c1) && (sxv[s] < xint));
                        c0[s] = c1;
                    }
                    e = e1;
                }
                #pragma unroll
                for (int s = 0; s < 4; s++) {
                    const float dist   = sqrtf(mind2[s]);
                    const float stroke = fminf(fmaxf(fmaf(wa[p], 0.5f, 0.5f) - dist, 0.0f), 1.0f);
                    const float cov    = fmaxf((float)(nc[s] & 1), stroke);
                    val[s] *= 1.0f - wa[2 + p] * cov;
                }
            }
            const float acc = (val[0] + val[1]) + (val[2] + val[3]);
            out[OUT_R + b * 784 + px] = 1.0f - 0.25f * acc;
        }
    }

    cluster_sync_all();
}

// ---------------------------------------------------------------------------
extern "C" void kernel_launch(void* const* d_in, const int* in_sizes, int n_in,
                              void* d_out, int out_size)
{
    const float* x    = (const float*)d_in[0];
    const float* eps  = (const float*)d_in[1];
    const float* ew1  = (const float*)d_in[2];
    const float* eb1  = (const float*)d_in[3];
    const float* ew2  = (const float*)d_in[4];
    const float* eb2  = (const float*)d_in[5];
    const float* muw  = (const float*)d_in[6];
    const float* mub  = (const float*)d_in[7];
    const float* lvw  = (const float*)d_in[8];
    const float* lvb  = (const float*)d_in[9];
    const float* dw1  = (const float*)d_in[10];
    const float* db1  = (const float*)d_in[11];
    const float* dw2  = (const float*)d_in[12];
    const float* db2  = (const float*)d_in[13];
    const float* cpw  = (const float*)d_in[14];
    const float* cpb  = (const float*)d_in[15];
    const float* rw1  = (const float*)d_in[16];
    const float* rb1  = (const float*)d_in[17];
    const float* rw2  = (const float*)d_in[18];
    const float* rb2  = (const float*)d_in[19];
    const float* wdw  = (const float*)d_in[20];
    const float* wdb  = (const float*)d_in[21];
    const float* alw  = (const float*)d_in[22];
    const float* alb  = (const float*)d_in[23];
    float* out = (float*)d_out;

    const int dyn = NSTAGES * STAGE_BYTES;   // 196608 bytes
    cudaFuncSetAttribute(fused_kernel, cudaFuncAttributeMaxDynamicSharedMemorySize, dyn);
    fused_kernel<<<BATCH, TPB, dyn>>>(x, eps, ew1, eb1, ew2, eb2, muw, mub, lvw, lvb,
                                      dw1, db1, dw2, db2, cpw, cpb, rw1, rb1, rw2, rb2,
                                      wdw, wdb, alw, alb, out);
}

// round 8
// speedup vs baseline: 4.2059x; 1.0463x over previous
#include <cuda_runtime.h>
#include <math.h>
#include <stdint.h>

// ---------------------------------------------------------------------------
// HierarchicalVAE fused: cluster-4 multicast weight streaming, warp-specialized
// producer, MLP on 512 threads, rasterizer on 784 threads (1 px/thread).
// grid = 128 CTAs (1 per batch), 32 clusters x 4 CTAs, 832 threads:
//   warps 0-15 (tid 0-511):   MLP chain (tile consumers) + raster
//   warps 16-24 (tid 512-799): park at raster gate, then raster
//   warp 25 (tid 800):         producer - 44 tiles, 3-stage x 64KB ring
// Named barrier 1 (512 thr) = MLP sync; barrier 2 (800 thr) = raster gate.
// ---------------------------------------------------------------------------

#define BATCH 128
#define TPB 832
#define NC 512                      // MLP consumer threads
#define NGATE 800                   // warps 0-24 at raster gate
#define CLUSTER 4
#define NSTAGES 3
#define STAGE_FLOATS 16384          // 64KB
#define STAGE_BYTES  65536
#define NT 44
#define HALFC 14.0f
#define SCALEC 12.0f

#define OUT_R  0
#define OUT_MU (BATCH*784)
#define OUT_LV (OUT_MU + BATCH*64)
#define OUT_CP (OUT_LV + BATCH*64)
#define OUT_W  (OUT_CP + BATCH*64)
#define OUT_A  (OUT_W + BATCH*2)

struct WPtrs {
    const float *ew1, *ew2, *muw, *lvw, *dw1, *dw2, *cpw, *wdw, *alw, *rw1, *rw2;
};

__device__ __forceinline__ uint32_t smem_u32(const void* p) {
    return (uint32_t)__cvta_generic_to_shared(p);
}
__device__ __forceinline__ void mbar_init(uint32_t addr, uint32_t count) {
    asm volatile("mbarrier.init.shared.b64 [%0], %1;" :: "r"(addr), "r"(count) : "memory");
}
__device__ __forceinline__ void mbar_wait(uint32_t addr, uint32_t parity) {
    asm volatile(
        "{\n\t.reg .pred P;\n"
        "W_%=:\n\t"
        "mbarrier.try_wait.parity.acquire.cta.shared::cta.b64 P, [%0], %1, 0x989680;\n\t"
        "@P bra.uni D_%=;\n\t"
        "bra.uni W_%=;\n"
        "D_%=:\n\t}"
        :: "r"(addr), "r"(parity) : "memory");
}
__device__ __forceinline__ void mbar_expect_tx(uint32_t addr, uint32_t bytes) {
    asm volatile("mbarrier.arrive.expect_tx.shared.b64 _, [%0], %1;"
                 :: "r"(addr), "r"(bytes) : "memory");
}
__device__ __forceinline__ void mbar_arrive_rank(uint32_t addr, uint32_t rank) {
    asm volatile(
        "{\n\t.reg .b32 ra;\n\t"
        "mapa.shared::cluster.u32 ra, %0, %1;\n\t"
        "mbarrier.arrive.shared::cluster.b64 _, [ra];\n\t}"
        :: "r"(addr), "r"(rank) : "memory");
}
__device__ __forceinline__ void cluster_sync_all() {
    asm volatile("barrier.cluster.arrive.aligned;" ::: "memory");
    asm volatile("barrier.cluster.wait.aligned;" ::: "memory");
}
__device__ __forceinline__ void bulk_mc(uint32_t dst, const void* src, uint32_t bytes,
                                        uint32_t mbar, uint16_t mask) {
    asm volatile(
        "cp.async.bulk.shared::cluster.global.mbarrier::complete_tx::bytes.multicast::cluster "
        "[%0], [%1], %2, [%3], %4;"
        :: "r"(dst), "l"(src), "r"(bytes), "r"(mbar), "h"(mask) : "memory");
}

__device__ __forceinline__ float seluf(float x) {
    const float sc = 1.0507009873554805f;
    const float al = 1.6732632423543772f;
    return x > 0.0f ? sc * x : sc * al * (expf(x) - 1.0f);
}
__device__ __forceinline__ float lrelu(float x) { return x >= 0.0f ? x : 0.2f * x; }
__device__ __forceinline__ float sigm(float x)  { return 1.0f / (1.0f + expf(-x)); }

// Tile table (44 tiles, 64KB stages) — identical to R6/R7.
__device__ __forceinline__ int tile_segs(int n, const WPtrs& p,
                                         const char* srcs[2], uint32_t szs[2]) {
    if (n < 13) { int r0 = n * 64; int rows = (r0 + 64 <= 784) ? 64 : (784 - r0);
                  srcs[0] = (const char*)(p.ew1 + r0 * 256); szs[0] = rows * 1024; return 1; }
    n -= 13;
    if (n < 4)  { srcs[0] = (const char*)(p.ew2 + n * 64 * 256); szs[0] = 65536; return 1; }
    n -= 4;
    if (n == 0) { srcs[0] = (const char*)p.muw; szs[0] = 65536; return 1; } n--;
    if (n == 0) { srcs[0] = (const char*)p.lvw; szs[0] = 65536; return 1; } n--;
    if (n < 2)  { srcs[0] = (const char*)(p.dw1 + n * 32 * 512); szs[0] = 65536; return 1; }
    n -= 2;
    if (n < 16) { srcs[0] = (const char*)(p.dw2 + n * 32 * 512); szs[0] = 65536; return 1; }
    n -= 16;
    if (n == 0) { srcs[0] = (const char*)p.cpw; szs[0] = 57344; return 1; } n--;
    if (n == 0) { srcs[0] = (const char*)p.wdw; szs[0] = 4096;
                  srcs[1] = (const char*)p.alw; szs[1] = 4096; return 2; } n--;
    if (n < 3)  { int r0 = n * 32; int rows = (r0 + 32 <= 92) ? 32 : (92 - r0);
                  srcs[0] = (const char*)(p.rw1 + r0 * 512); szs[0] = rows * 2048; return 1; }
    n -= 3;
    srcs[0] = (const char*)(p.rw2 + n * 256 * 52); szs[0] = 53248; return 1;
}

__device__ __forceinline__ void produce(int j, uint32_t bar_base, uint32_t ring_base,
                                        const WPtrs& p, uint32_t rank) {
    const int s = j % NSTAGES;
    mbar_wait(bar_base + s * 16 + 8, 1u ^ ((uint32_t)(j / NSTAGES) & 1u));
    const char* srcs[2]; uint32_t szs[2];
    int ns = tile_segs(j, p, srcs, szs);
    uint32_t total = szs[0] + ((ns > 1) ? szs[1] : 0u);
    const uint32_t full = bar_base + s * 16;
    mbar_expect_tx(full, total);
    uint32_t dst = ring_base + s * STAGE_BYTES;
    for (int k = 0; k < ns; k++) {
        uint32_t slice = szs[k] >> 2;   // /CLUSTER
        bulk_mc(dst + rank * slice, srcs[k] + rank * slice, slice, full, 0xF);
        dst += szs[k];
    }
}

#define CONS_SYNC() asm volatile("bar.sync 1, %0;" :: "n"(NC) : "memory")
#define GATE_SYNC() asm volatile("bar.sync 2, %0;" :: "n"(NGATE) : "memory")

#define TILE_BEGIN() do { \
        mbar_wait(bar_base + (tn % NSTAGES) * 16, (uint32_t)(tn / NSTAGES) & 1u); \
        ws = wb + (tn % NSTAGES) * STAGE_FLOATS; } while (0)

#define TILE_END() do { __syncwarp(); \
        if ((tid & 31) == 0) { uint32_t e = bar_base + (tn % NSTAGES) * 16 + 8; \
            mbar_arrive_rank(e, 0); mbar_arrive_rank(e, 1); \
            mbar_arrive_rank(e, 2); mbar_arrive_rank(e, 3); } \
        tn++; } while (0)

__global__ void __launch_bounds__(TPB, 1) __cluster_dims__(CLUSTER, 1, 1)
fused_kernel(
    const float* __restrict__ x,    const float* __restrict__ eps,
    const float* __restrict__ ew1,  const float* __restrict__ eb1,
    const float* __restrict__ ew2,  const float* __restrict__ eb2,
    const float* __restrict__ muw,  const float* __restrict__ mub,
    const float* __restrict__ lvw,  const float* __restrict__ lvb,
    const float* __restrict__ dw1,  const float* __restrict__ db1,
    const float* __restrict__ dw2,  const float* __restrict__ db2,
    const float* __restrict__ cpw,  const float* __restrict__ cpb,
    const float* __restrict__ rw1,  const float* __restrict__ rb1,
    const float* __restrict__ rw2w, const float* __restrict__ rb2,
    const float* __restrict__ wdw,  const float* __restrict__ wdb,
    const float* __restrict__ alw,  const float* __restrict__ alb,
    float* __restrict__ out)
{
    extern __shared__ float wb[];   // NSTAGES * STAGE_FLOATS

    const int b   = blockIdx.x;
    const int tid = threadIdx.x;

    __shared__ alignas(16) unsigned long long mbars[NSTAGES * 2];
    __shared__ float sx[784];
    __shared__ float h1[256];
    __shared__ float h2[256];
    __shared__ float muv[64];
    __shared__ float hin[92];
    __shared__ float d1[512];
    __shared__ float d2[512];
    __shared__ float r1[512];
    __shared__ float pts[52];
    __shared__ float red[NC];
    __shared__ float red2[NC];
    __shared__ float qx[64], qy[64], wa[4];
    __shared__ alignas(16) float4 pt4[64];   // (x, y, |q|^2, 1/dy)

    WPtrs wp; wp.ew1 = ew1; wp.ew2 = ew2; wp.muw = muw; wp.lvw = lvw;
    wp.dw1 = dw1; wp.dw2 = dw2; wp.cpw = cpw; wp.wdw = wdw; wp.alw = alw;
    wp.rw1 = rw1; wp.rw2 = rw2w;

    const uint32_t bar_base  = smem_u32(mbars);
    const uint32_t ring_base = smem_u32(wb);
    uint32_t rank;
    asm("mov.u32 %0, %%cluster_ctarank;" : "=r"(rank));

    if (tid == 0) {
        #pragma unroll
        for (int s = 0; s < NSTAGES; s++) {
            mbar_init(bar_base + s * 16, 1);         // full: 1 expect_tx arrive
            mbar_init(bar_base + s * 16 + 8, 64);    // empty: 16 MLP warps x 4 CTAs
        }
    }
    __syncthreads();
    cluster_sync_all();

    if (tid >= NGATE) {
        // ---------------- producer warp (warp 25) ----------------
        if (tid == NGATE) {
            for (int j = 0; j < NT; j++) produce(j, bar_base, ring_base, wp, rank);
        }
    } else {
        if (tid < NC) {
            // ---------------- MLP (512 threads, 16 warps) ----------------
            for (int i = tid; i < 784; i += NC) sx[i] = x[b * 784 + i];
            CONS_SYNC();

            int tn = 0;
            float* ws;

            // enc1: 784 -> 256 (13 tiles), 2-way K split
            {
                const int g = tid >> 8, o = tid & 255;
                float acc = (g == 0) ? eb1[o] : 0.0f;
                for (int t = 0; t < 13; t++) {
                    TILE_BEGIN();
                    const int rows = (t < 12) ? 64 : 16, half = rows >> 1;
                    const int r0 = g * half, gr = t * 64 + r0;
                    #pragma unroll 8
                    for (int r = 0; r < half; r++)
                        acc = fmaf(sx[gr + r], ws[(r0 + r) * 256 + o], acc);
                    TILE_END();
                }
                red[tid] = acc;
            }
            CONS_SYNC();
            if (tid < 256) h1[tid] = lrelu(red[tid] + red[256 + tid]);
            CONS_SYNC();

            // enc2: 256 -> 256 (4 tiles), 2-way K split
            {
                const int g = tid >> 8, o = tid & 255;
                float acc = (g == 0) ? eb2[o] : 0.0f;
                for (int t = 0; t < 4; t++) {
                    TILE_BEGIN();
                    const int r0 = g * 32, gr = t * 64 + r0;
                    #pragma unroll 8
                    for (int r = 0; r < 32; r++)
                        acc = fmaf(h1[gr + r], ws[(r0 + r) * 256 + o], acc);
                    TILE_END();
                }
                red[tid] = acc;
            }
            CONS_SYNC();
            if (tid < 256) h2[tid] = lrelu(red[tid] + red[256 + tid]);
            CONS_SYNC();

            // mu: 256 -> 64 (1 tile), 8-way K split
            {
                const int g = tid >> 6, l = tid & 63;
                TILE_BEGIN();
                float a = 0.0f;
                #pragma unroll 8
                for (int i = 0; i < 32; i++) {
                    int kl = g * 32 + i;
                    a = fmaf(h2[kl], ws[kl * 64 + l], a);
                }
                red[tid] = a;
                TILE_END();
            }
            CONS_SYNC();
            if (tid < 64) {
                float s = mub[tid];
                #pragma unroll
                for (int k = 0; k < 8; k++) s += red[k * 64 + tid];
                muv[tid] = s;
            }
            CONS_SYNC();

            // logvar: 256 -> 64 (1 tile), 8-way K split
            {
                const int g = tid >> 6, l = tid & 63;
                TILE_BEGIN();
                float a = 0.0f;
                #pragma unroll 8
                for (int i = 0; i < 32; i++) {
                    int kl = g * 32 + i;
                    a = fmaf(h2[kl], ws[kl * 64 + l], a);
                }
                red[tid] = a;
                TILE_END();
            }
            CONS_SYNC();
            if (tid < 64) {
                float lvV = lvb[tid];
                #pragma unroll
                for (int k = 0; k < 8; k++) lvV += red[k * 64 + tid];
                float m = muv[tid];
                out[OUT_MU + b * 64 + tid] = m;
                out[OUT_LV + b * 64 + tid] = lvV;
                hin[tid] = m + eps[b * 64 + tid] * expf(0.5f * lvV);
            }
            CONS_SYNC();

            // dec1: 64 -> 512 (2 tiles of 32 rows)
            {
                float a = db1[tid];
                for (int t = 0; t < 2; t++) {
                    TILE_BEGIN();
                    const int r0 = t * 32;
                    #pragma unroll 8
                    for (int r = 0; r < 32; r++)
                        a = fmaf(hin[r0 + r], ws[r * 512 + tid], a);
                    TILE_END();
                }
                d1[tid] = seluf(a);
            }
            CONS_SYNC();

            // dec2: 512 -> 512 (16 tiles of 32 rows)
            {
                float a = db2[tid];
                for (int t = 0; t < 16; t++) {
                    TILE_BEGIN();
                    const int r0 = t * 32;
                    #pragma unroll 8
                    for (int r = 0; r < 32; r++)
                        a = fmaf(d1[r0 + r], ws[r * 512 + tid], a);
                    TILE_END();
                }
                d2[tid] = seluf(a);
            }
            CONS_SYNC();

            // coarse cp: 512 -> 28 (1 tile), 16-way K split
            {
                const int g = tid >> 5, l = tid & 31;
                TILE_BEGIN();
                float a = 0.0f;
                if (l < 28) {
                    #pragma unroll 8
                    for (int i = 0; i < 32; i++) {
                        int kl = g * 32 + i;
                        a = fmaf(d2[kl], ws[kl * 28 + l], a);
                    }
                }
                red[tid] = a;
                TILE_END();
            }
            CONS_SYNC();
            if (tid < 28) {
                float s = cpb[tid];
                #pragma unroll
                for (int k = 0; k < 16; k++) s += red[k * 32 + tid];
                hin[64 + tid] = tanhf(s);
            }
            CONS_SYNC();

            // widths + alphas: 512 -> 2 each (1 fused tile)
            {
                const int pp = tid >> 8, l = tid & 255;
                TILE_BEGIN();
                float aw = fmaf(d2[l], ws[l * 2 + pp], 0.0f);
                aw = fmaf(d2[l + 256], ws[(l + 256) * 2 + pp], aw);
                float aa = fmaf(d2[l], ws[1024 + l * 2 + pp], 0.0f);
                aa = fmaf(d2[l + 256], ws[1024 + (l + 256) * 2 + pp], aa);
                red[tid] = aw; red2[tid] = aa;
                TILE_END();
            }
            CONS_SYNC();
            if (tid < 2) {
                const float* rp = &red[tid * 256];
                float s0 = 0, s1 = 0, s2 = 0, s3 = 0;
                #pragma unroll
                for (int j = 0; j < 64; j++) { s0 += rp[j]; s1 += rp[64 + j]; s2 += rp[128 + j]; s3 += rp[192 + j]; }
                float wv = sigm(wdb[tid] + ((s0 + s1) + (s2 + s3))) * 2.0f + 1.0f;
                wa[tid] = wv;
                out[OUT_W + b * 2 + tid] = wv;
            } else if (tid >= 32 && tid < 34) {
                const int pA = tid - 32;
                const float* rp = &red2[pA * 256];
                float s0 = 0, s1 = 0, s2 = 0, s3 = 0;
                #pragma unroll
                for (int j = 0; j < 64; j++) { s0 += rp[j]; s1 += rp[64 + j]; s2 += rp[128 + j]; s3 += rp[192 + j]; }
                float av = sigm(alb[pA] + ((s0 + s1) + (s2 + s3)));
                wa[2 + pA] = av;
                out[OUT_A + b * 2 + pA] = av;
            }
            CONS_SYNC();

            // refine1: 92 -> 512 (3 tiles)
            {
                float a = rb1[tid];
                for (int t = 0; t < 3; t++) {
                    TILE_BEGIN();
                    const int r0 = t * 32, rows = (t < 2) ? 32 : 28;
                    #pragma unroll 8
                    for (int r = 0; r < rows; r++)
                        a = fmaf(hin[r0 + r], ws[r * 512 + tid], a);
                    TILE_END();
                }
                r1[tid] = seluf(a);
            }
            CONS_SYNC();

            // refine2: 512 -> 52 (2 tiles of 256 rows), 8-way K split
            {
                const int g = tid >> 6, l = tid & 63;
                float a = 0.0f;
                for (int t = 0; t < 2; t++) {
                    TILE_BEGIN();
                    if (l < 52) {
                        #pragma unroll 8
                        for (int i = 0; i < 32; i++) {
                            int kl = g * 32 + i;
                            a = fmaf(r1[t * 256 + kl], ws[kl * 52 + l], a);
                        }
                    }
                    TILE_END();
                }
                red[tid] = a;
            }
            CONS_SYNC();
            if (tid < 52) {
                float s = rb2[tid];
                #pragma unroll
                for (int k = 0; k < 8; k++) s += red[k * 64 + tid];
                pts[tid] = tanhf(s) * SCALEC + HALFC;
            }
            CONS_SYNC();

            // control points out + bezier sample eval
            if (tid < 64) {
                const int p = tid >> 5, rem = tid & 31;
                {
                    int s = rem >> 3, k = (rem >> 1) & 3, d = rem & 1;
                    out[OUT_CP + b * 64 + tid] = pts[p * 26 + (3 * s + k) * 2 + d];
                }
                const int ss = rem >> 3, ti = rem & 7;
                float t  = (float)ti / 7.0f;
                float mt = 1.0f - t;
                float b0 = mt * mt * mt;
                float b1 = 3.0f * mt * mt * t;
                float b2 = 3.0f * mt * t * t;
                float b3 = t * t * t;
                int base = p * 26 + (3 * ss) * 2;
                float X = b0 * pts[base + 0] + b1 * pts[base + 2] + b2 * pts[base + 4] + b3 * pts[base + 6];
                float Y = b0 * pts[base + 1] + b1 * pts[base + 3] + b2 * pts[base + 5] + b3 * pts[base + 7];
                qx[tid] = X; qy[tid] = Y;
            }
            CONS_SYNC();
            if (tid < 64) {
                const int p = tid >> 5, m = tid & 31;
                float X = qx[tid], Y = qy[tid];
                float y1 = qy[p * 32 + ((m + 1) & 31)];
                float si = __fdiv_rn(1.0f, (y1 - Y) + 1e-8f);
                pt4[tid] = make_float4(X, Y, X * X + Y * Y, si);
            }
        }

        // ---------------- raster gate: warps 0-24 join ----------------
        GATE_SYNC();

        // ---------------- rasterizer: 1 pixel per thread ----------------
        if (tid < 784) {
            const int px = tid;
            const int pi = px / 28, pj = px - pi * 28;
            float syv[4], sxv[4], nxv[4], nyv[4], ssn[4], val[4];
            #pragma unroll
            for (int s = 0; s < 4; s++) {
                syv[s] = (float)pi + (0.25f + 0.5f * (float)(s >> 1));
                sxv[s] = (float)pj + (0.25f + 0.5f * (float)(s & 1));
                nxv[s] = -2.0f * sxv[s];
                nyv[s] = -2.0f * syv[s];
                ssn[s] = sxv[s] * sxv[s] + syv[s] * syv[s];
                val[s] = 1.0f;
            }
            #pragma unroll
            for (int p = 0; p < 2; p++) {
                const int base = p * 32;
                float mind2[4]; int nc[4]; bool c0[4];
                float4 e = pt4[base];
                #pragma unroll
                for (int s = 0; s < 4; s++) {
                    mind2[s] = 3.402823e38f; nc[s] = 0; c0[s] = e.y > syv[s];
                }
                #pragma unroll 8
                for (int m = 0; m < 32; m++) {
                    const float4 e1 = pt4[base + ((m + 1) & 31)];
                    const float dx = e1.x - e.x;
                    #pragma unroll
                    for (int s = 0; s < 4; s++) {
                        // clamp hoisted out of loop: min(max(v,0)) == max(min(v),0)
                        float v = fmaf(nxv[s], e.x, fmaf(nyv[s], e.y, e.z + ssn[s]));
                        mind2[s] = fminf(mind2[s], v);
                        const bool c1 = e1.y > syv[s];
                        const float xint = fmaf((syv[s] - e.y) * e.w, dx, e.x);
                        nc[s] += (int)((c0[s] != c1) && (sxv[s] < xint));
                        c0[s] = c1;
                    }
                    e = e1;
                }
                #pragma unroll
                for (int s = 0; s < 4; s++) {
                    const float dist   = sqrtf(fmaxf(mind2[s], 0.0f));
                    const float stroke = fminf(fmaxf(fmaf(wa[p], 0.5f, 0.5f) - dist, 0.0f), 1.0f);
                    const float cov    = fmaxf((float)(nc[s] & 1), stroke);
                    val[s] *= 1.0f - wa[2 + p] * cov;
                }
            }
            const float acc = (val[0] + val[1]) + (val[2] + val[3]);
            out[OUT_R + b * 784 + px] = 1.0f - 0.25f * acc;
        }
    }

    cluster_sync_all();
}

// ---------------------------------------------------------------------------
extern "C" void kernel_launch(void* const* d_in, const int* in_sizes, int n_in,
                              void* d_out, int out_size)
{
    const float* x    = (const float*)d_in[0];
    const float* eps  = (const float*)d_in[1];
    const float* ew1  = (const float*)d_in[2];
    const float* eb1  = (const float*)d_in[3];
    const float* ew2  = (const float*)d_in[4];
    const float* eb2  = (const float*)d_in[5];
    const float* muw  = (const float*)d_in[6];
    const float* mub  = (const float*)d_in[7];
    const float* lvw  = (const float*)d_in[8];
    const float* lvb  = (const float*)d_in[9];
    const float* dw1  = (const float*)d_in[10];
    const float* db1  = (const float*)d_in[11];
    const float* dw2  = (const float*)d_in[12];
    const float* db2  = (const float*)d_in[13];
    const float* cpw  = (const float*)d_in[14];
    const float* cpb  = (const float*)d_in[15];
    const float* rw1  = (const float*)d_in[16];
    const float* rb1  = (const float*)d_in[17];
    const float* rw2  = (const float*)d_in[18];
    const float* rb2  = (const float*)d_in[19];
    const float* wdw  = (const float*)d_in[20];
    const float* wdb  = (const float*)d_in[21];
    const float* alw  = (const float*)d_in[22];
    const float* alb  = (const float*)d_in[23];
    float* out = (float*)d_out;

    const int dyn = NSTAGES * STAGE_BYTES;   // 196608 bytes
    cudaFuncSetAttribute(fused_kernel, cudaFuncAttributeMaxDynamicSharedMemorySize, dyn);
    fused_kernel<<<BATCH, TPB, dyn>>>(x, eps, ew1, eb1, ew2, eb2, muw, mub, lvw, lvb,
                                      dw1, db1, dw2, db2, cpw, cpb, rw1, rb1, rw2, rb2,
                                      wdw, wdb, alw, alb, out);
}